// round 8
// baseline (speedup 1.0000x reference)
#include <cuda_runtime.h>
#include <math.h>
#include <stdint.h>

// Problem dims (fixed per setup_inputs)
#define B_   4
#define T_   4096
#define K_   1024          // Din == D == 1024
#define D_   1024
#define M_   (B_*T_)       // 16384

// ---------------- scratch (device globals; no allocations allowed) ---------
__device__ float g_buf0[(size_t)M_ * D_];   // 64 MB
__device__ float g_buf1[(size_t)M_ * D_];   // 64 MB
__device__ float g_buf2[(size_t)M_ * D_];   // 64 MB
__device__ float g_wT[(size_t)5 * K_ * D_]; // 20 MB transposed + tf32-rounded weights

#define CHUNK 32
#define NC    (T_/CHUNK)    // 128
__device__ float g_cA[B_*NC*D_];
__device__ float g_cP[B_*NC*D_];
__device__ float g_cC[B_*NC*D_];

// ---------------- helpers ----------------------------------------------------
__device__ __forceinline__ uint32_t cvt_tf32(float x) {
    uint32_t t; asm("cvt.rna.tf32.f32 %0, %1;" : "=r"(t) : "f"(x)); return t;
}
__device__ __forceinline__ uint32_t smem_u32(const void* p) {
    uint32_t a;
    asm("{ .reg .u64 t; cvta.to.shared.u64 t, %1; cvt.u32.u64 %0, t; }" : "=r"(a) : "l"(p));
    return a;
}
__device__ __forceinline__ void cp_async16(uint32_t saddr, const void* gptr) {
    asm volatile("cp.async.cg.shared.global [%0], [%1], 16;" :: "r"(saddr), "l"(gptr));
}
#define CP_COMMIT() asm volatile("cp.async.commit_group;" ::: "memory")
#define CP_WAIT1()  asm volatile("cp.async.wait_group 1;"  ::: "memory")
#define CP_WAIT0()  asm volatile("cp.async.wait_group 0;"  ::: "memory")

#define LDSM_X4(r0, r1, r2, r3, addr) \
    asm volatile("ldmatrix.sync.aligned.m8n8.x4.shared.b16 {%0,%1,%2,%3}, [%4];" \
                 : "=r"(r0), "=r"(r1), "=r"(r2), "=r"(r3) : "r"(addr))

__device__ __forceinline__ void mma_tf32(float c[4], const uint32_t a[4],
                                         uint32_t b0, uint32_t b1) {
    asm volatile(
        "mma.sync.aligned.m16n8k8.row.col.f32.tf32.tf32.f32 "
        "{%0,%1,%2,%3}, {%4,%5,%6,%7}, {%8,%9}, {%0,%1,%2,%3};"
        : "+f"(c[0]), "+f"(c[1]), "+f"(c[2]), "+f"(c[3])
        : "r"(a[0]), "r"(a[1]), "r"(a[2]), "r"(a[3]), "r"(b0), "r"(b1));
}

// ---------------- persistent tf32 mma.sync GEMM -------------------------------
// CTA tile 128x128, BK=32; 3-stage cp.async pipeline runs FLAT across a CTA's
// tile list (no drain at tile boundaries: next tile prefetch overlaps epilogue).
// 8 warps (2M x 4N), warp 64x32; LDSM + register double-buffer; XOR swizzle.

#define BMm 128
#define BNm 128
#define BKm 32
#define STEPSm (K_/BKm)        // 32
#define STAGE_B 16384          // 128 rows * 128 bytes
#define NSTG 3
#define GEMM_SMEM (2*NSTG*STAGE_B)   // 98304 B

enum { MODE_GATES = 0, MODE_BIAS = 2, MODE_GELU = 3, MODE_RESID = 4 };

template <int MODE, bool GATES>
__global__ __launch_bounds__(256, 2)
void tgemm_p(const float* __restrict__ A,      // [M,1024] tf32 bits
             const float* __restrict__ Wt,     // GATES: 2x[1024,1024]; else [1024,1024]
             const float* __restrict__ bias0,  // GATES: [2,1024]; else [1024]
             const float* __restrict__ extra,  // rnn_start[M] (GATES) or residual (RESID)
             float* __restrict__ C0,           // output (GATES: v)
             float* __restrict__ C2)           // GATES: f ; BIAS: tf32 copy
{
    extern __shared__ float smf[];
    const uint32_t sbase = smem_u32(smf);
    const uint32_t aB = sbase, bB = sbase + NSTG * STAGE_B;

    const int tid = threadIdx.x, lane = tid & 31, wid = tid >> 5;
    const int wm = wid >> 2, wn = wid & 3;
    const int bid = blockIdx.x, gsz = gridDim.x;

    const int NT  = GATES ? 2048 : 1024;
    const int nT  = (NT - bid + gsz - 1) / gsz;
    const int tot = nT * STEPSm;

    // cp.async mapping: 4 x 16B per matrix per stage per thread, swizzled cols
    const int r0 = tid >> 3;
    const int c4 = (tid & 7) << 2;
    const uint32_t soff0 = ((uint32_t)r0 << 7) + ((((uint32_t)c4) << 2) ^ (((uint32_t)r0 & 7) << 4));

    // LDSM per-lane constants
    const int rr = lane & 7;
    const uint32_t swz   = (uint32_t)rr << 4;
    const uint32_t akoff = (uint32_t)((lane >> 4) & 1) << 4;
    const uint32_t bkoff = (uint32_t)((lane >> 3) & 1) << 4;
    const int a_row8 = (lane >> 3) & 1;
    const int b_n8   = (lane >> 4) & 1;
    uint32_t aoff[4];
#pragma unroll
    for (int mi = 0; mi < 4; mi++)
        aoff[mi] = (uint32_t)(wm * 64 + mi * 16 + a_row8 * 8 + rr) << 7;
    uint32_t boff[2];
#pragma unroll
    for (int j = 0; j < 2; j++)
        boff[j] = (uint32_t)(wn * 32 + j * 16 + b_n8 * 8 + rr) << 7;

    float acc[4][4][4];
#pragma unroll
    for (int mi = 0; mi < 4; mi++)
#pragma unroll
        for (int ni = 0; ni < 4; ni++)
#pragma unroll
            for (int q = 0; q < 4; q++) acc[mi][ni][q] = 0.f;

    uint32_t af[2][4][4];
    uint32_t bq[2][2][4];

#define TILE_OF(GT) (bid + ((GT) >> 5) * gsz)

#define ISSUE_STEP(GT) do {                                                     \
        const int _tile = TILE_OF(GT);                                          \
        int _bm, _bn;                                                           \
        const float* _Bb;                                                       \
        if (GATES) {                                                            \
            _bm = _tile >> 4; _bn = (_tile >> 1) & 7;                           \
            _Bb = Wt + (size_t)(_tile & 1) * K_ * D_ + (size_t)_bn * BNm * K_;  \
        } else {                                                                \
            _bm = _tile >> 3; _bn = _tile & 7;                                  \
            _Bb = Wt + (size_t)_bn * BNm * K_;                                  \
        }                                                                       \
        const float* _Ab = A + (size_t)_bm * BMm * K_;                          \
        const int _k0 = ((GT) & 31) * BKm;                                      \
        const uint32_t _sa = aB + ((GT) % NSTG) * STAGE_B + soff0;              \
        const uint32_t _sb = bB + ((GT) % NSTG) * STAGE_B + soff0;              \
        _Pragma("unroll")                                                       \
        for (int j = 0; j < 4; j++) {                                           \
            const size_t go = (size_t)(r0 + 32 * j) * K_ + _k0 + c4;            \
            const uint32_t so = (uint32_t)(32 * j) << 7;                        \
            cp_async16(_sa + so, _Ab + go);                                     \
            cp_async16(_sb + so, _Bb + go);                                     \
        }                                                                       \
    } while (0)

#define LOAD_FRAGS(SLOT, SA, SB, KO) do {                                       \
        const uint32_t _ax = ((KO) + akoff) ^ swz;                              \
        const uint32_t _bx = ((KO) + bkoff) ^ swz;                              \
        _Pragma("unroll")                                                       \
        for (int mi = 0; mi < 4; mi++)                                          \
            LDSM_X4(af[SLOT][mi][0], af[SLOT][mi][1],                           \
                    af[SLOT][mi][2], af[SLOT][mi][3], (SA) + aoff[mi] + _ax);   \
        _Pragma("unroll")                                                       \
        for (int j = 0; j < 2; j++)                                             \
            LDSM_X4(bq[SLOT][j][0], bq[SLOT][j][1],                             \
                    bq[SLOT][j][2], bq[SLOT][j][3], (SB) + boff[j] + _bx);      \
    } while (0)

    ISSUE_STEP(0); CP_COMMIT();
    ISSUE_STEP(1); CP_COMMIT();
    CP_WAIT1();
    __syncthreads();

    uint32_t sa = aB, sb = bB;
    LOAD_FRAGS(0, sa, sb, 0u);

    for (int gt = 0; gt < tot; gt++) {
#pragma unroll
        for (int ks = 0; ks < 4; ks++) {
            if (ks < 3) {
                LOAD_FRAGS((ks + 1) & 1, sa, sb, (uint32_t)(ks + 1) * 32);
            } else if (gt + 1 < tot) {
                if (gt + 2 < tot) { ISSUE_STEP(gt + 2); CP_COMMIT(); CP_WAIT1(); }
                else              { CP_WAIT0(); }
                __syncthreads();
                sa = aB + ((gt + 1) % NSTG) * STAGE_B;
                sb = bB + ((gt + 1) % NSTG) * STAGE_B;
                LOAD_FRAGS(0, sa, sb, 0u);
            }
            const int p = ks & 1;
#pragma unroll
            for (int mi = 0; mi < 4; mi++)
#pragma unroll
                for (int ni = 0; ni < 4; ni++)
                    mma_tf32(acc[mi][ni], af[p][mi],
                             bq[p][ni >> 1][(ni & 1) * 2],
                             bq[p][ni >> 1][(ni & 1) * 2 + 1]);
        }

        if ((gt & 31) == 31) {
            // -------- epilogue for this tile (overlaps next tile's cp.async)
            const int tile = TILE_OF(gt);
            int bm, bn, z;
            if (GATES) { z = tile & 1; bn = (tile >> 1) & 7; bm = tile >> 4; }
            else       { z = 0;        bn = tile & 7;        bm = tile >> 3; }
            const float* bias = GATES ? (bias0 + z * D_) : bias0;
            float* C = (GATES && z) ? C2 : C0;

            const int r_base = bm * BMm + wm * 64 + (lane >> 2);
            const int c_base = bn * BNm + wn * 32 + ((lane & 3) << 1);
#pragma unroll
            for (int mi = 0; mi < 4; mi++) {
                const int gr0 = r_base + mi * 16;
                const int gr1 = gr0 + 8;
                float rs0 = 0.f, rs1 = 0.f;
                if (GATES) { if (z) { rs0 = extra[gr0]; rs1 = extra[gr1]; } }
#pragma unroll
                for (int ni = 0; ni < 4; ni++) {
                    const int gc = c_base + ni * 8;
                    float b0 = bias[gc], b1 = bias[gc + 1];
                    float v0 = acc[mi][ni][0] + b0;
                    float v1 = acc[mi][ni][1] + b1;
                    float v2 = acc[mi][ni][2] + b0;
                    float v3 = acc[mi][ni][3] + b1;
                    if (GATES) {
                        if (z == 0) {
                            v0 = tanhf(v0); v1 = tanhf(v1);
                            v2 = tanhf(v2); v3 = tanhf(v3);
                        } else {
                            v0 = (1.f - rs0) / (1.f + expf(-v0));
                            v1 = (1.f - rs0) / (1.f + expf(-v1));
                            v2 = (1.f - rs1) / (1.f + expf(-v2));
                            v3 = (1.f - rs1) / (1.f + expf(-v3));
                        }
                    } else if (MODE == MODE_GELU) {
                        v0 = 0.5f * v0 * (1.f + erff(v0 * 0.70710678118654752f));
                        v1 = 0.5f * v1 * (1.f + erff(v1 * 0.70710678118654752f));
                        v2 = 0.5f * v2 * (1.f + erff(v2 * 0.70710678118654752f));
                        v3 = 0.5f * v3 * (1.f + erff(v3 * 0.70710678118654752f));
                        v0 = __uint_as_float(cvt_tf32(v0));
                        v1 = __uint_as_float(cvt_tf32(v1));
                        v2 = __uint_as_float(cvt_tf32(v2));
                        v3 = __uint_as_float(cvt_tf32(v3));
                    } else if (MODE == MODE_RESID) {
                        const float2 e0 = *reinterpret_cast<const float2*>(extra + (size_t)gr0 * D_ + gc);
                        const float2 e1 = *reinterpret_cast<const float2*>(extra + (size_t)gr1 * D_ + gc);
                        v0 += e0.x; v1 += e0.y; v2 += e1.x; v3 += e1.y;
                    }
                    *reinterpret_cast<float2*>(C + (size_t)gr0 * D_ + gc) = make_float2(v0, v1);
                    *reinterpret_cast<float2*>(C + (size_t)gr1 * D_ + gc) = make_float2(v2, v3);
                    if (!GATES && MODE == MODE_BIAS) {
                        float t0 = __uint_as_float(cvt_tf32(v0));
                        float t1 = __uint_as_float(cvt_tf32(v1));
                        float t2 = __uint_as_float(cvt_tf32(v2));
                        float t3 = __uint_as_float(cvt_tf32(v3));
                        *reinterpret_cast<float2*>(C2 + (size_t)gr0 * D_ + gc) = make_float2(t0, t1);
                        *reinterpret_cast<float2*>(C2 + (size_t)gr1 * D_ + gc) = make_float2(t2, t3);
                    }
                }
            }
#pragma unroll
            for (int mi = 0; mi < 4; mi++)
#pragma unroll
                for (int ni = 0; ni < 4; ni++)
#pragma unroll
                    for (int q = 0; q < 4; q++) acc[mi][ni][q] = 0.f;
        }
    }
#undef ISSUE_STEP
#undef LOAD_FRAGS
#undef TILE_OF
}

// ---------------- profiler-aim no-op (keeps gates GEMM at launch index 3) ----
__global__ void aim_kernel() { if (blockIdx.x == 0 && threadIdx.x == 0) g_cA[0] = 0.f; }

// ---------------- x -> tf32-rounded copy ------------------------------------
__global__ void cvt_x_kernel(const float* __restrict__ x, float* __restrict__ xt)
{
    int i = blockIdx.x * blockDim.x + threadIdx.x;
    float4 v = reinterpret_cast<const float4*>(x)[i];
    float4 o;
    o.x = __uint_as_float(cvt_tf32(v.x));
    o.y = __uint_as_float(cvt_tf32(v.y));
    o.z = __uint_as_float(cvt_tf32(v.z));
    o.w = __uint_as_float(cvt_tf32(v.w));
    reinterpret_cast<float4*>(xt)[i] = o;
}

// ---------------- weight transpose + tf32 rounding --------------------------
__global__ void transpose_tf32(const float* __restrict__ s0, const float* __restrict__ s1,
                               const float* __restrict__ s2, const float* __restrict__ s3,
                               const float* __restrict__ s4, float* __restrict__ dst)
{
    __shared__ float tile[32][33];
    const int z = blockIdx.z;
    const float* src = (z == 0) ? s0 : (z == 1) ? s1 : (z == 2) ? s2 : (z == 3) ? s3 : s4;
    float* d = dst + (size_t)z * K_ * D_;
    const int n0 = blockIdx.x * 32, k0 = blockIdx.y * 32;
    const int tx = threadIdx.x, ty = threadIdx.y;
#pragma unroll
    for (int r = 0; r < 32; r += 8)
        tile[ty + r][tx] = src[(size_t)(k0 + ty + r) * D_ + n0 + tx];
    __syncthreads();
#pragma unroll
    for (int r = 0; r < 32; r += 8) {
        uint32_t t = cvt_tf32(tile[tx][ty + r]);
        d[(size_t)(n0 + ty + r) * K_ + k0 + tx] = __uint_as_float(t);
    }
}

// ---------------- chunked scan ----------------------------------------------
__global__ void scan_pass1(const float* __restrict__ V, const float* __restrict__ F)
{
    int idx = blockIdx.x * blockDim.x + threadIdx.x;
    int d = idx % D_;
    int c = (idx / D_) % NC;
    int b = idx / (D_ * NC);
    size_t base = ((size_t)b * T_ + (size_t)c * CHUNK) * D_ + d;
    float A = 1.f, h = 0.f;
#pragma unroll 8
    for (int t = 0; t < CHUNK; t++) {
        float f = F[base + (size_t)t * D_];
        float v = V[base + (size_t)t * D_];
        A *= f;
        h = f * h + (1.f - f) * v;
    }
    g_cA[idx] = A;
    g_cP[idx] = h;
}

__global__ void scan_pass2(const float* __restrict__ hidden, float* __restrict__ hT_out)
{
    extern __shared__ float sh[];
    float* sA = sh;
    float* sP = sh + NC * 128;
    const int blk = blockIdx.x;
    const int b   = blk >> 3;
    const int d0  = (blk & 7) * 128;
#pragma unroll 4
    for (int j = 0; j < 64; j++) {
        int i  = threadIdx.x + 256 * j;
        int c  = i >> 7, dd = i & 127;
        size_t g = ((size_t)b * NC + c) * D_ + d0 + dd;
        sA[i] = g_cA[g];
        sP[i] = g_cP[g];
    }
    __syncthreads();
    if (threadIdx.x < 128) {
        const int dd = threadIdx.x;
        float h = hidden[(size_t)b * D_ + d0 + dd];
        for (int c = 0; c < NC; c++) {
            g_cC[((size_t)b * NC + c) * D_ + d0 + dd] = h;
            h = sA[c * 128 + dd] * h + sP[c * 128 + dd];
        }
        hT_out[(size_t)b * D_ + d0 + dd] = h;
    }
}

__global__ void scan_pass3(const float* __restrict__ V, const float* __restrict__ F,
                           float* __restrict__ HS)
{
    int idx = blockIdx.x * blockDim.x + threadIdx.x;
    int d = idx % D_;
    int c = (idx / D_) % NC;
    int b = idx / (D_ * NC);
    size_t base = ((size_t)b * T_ + (size_t)c * CHUNK) * D_ + d;
    float h = g_cC[idx];
#pragma unroll 8
    for (int t = 0; t < CHUNK; t++) {
        float f = F[base + (size_t)t * D_];
        float v = V[base + (size_t)t * D_];
        h = f * h + (1.f - f) * v;
        HS[base + (size_t)t * D_] = __uint_as_float(cvt_tf32(h));
    }
}

// ---------------- LayerNorm ---------------------------------------------------
__global__ __launch_bounds__(256)
void ln_kernel(const float* __restrict__ Z, const float* __restrict__ g,
               const float* __restrict__ b, float* __restrict__ out)
{
    int row = blockIdx.x;
    int t = threadIdx.x;
    float4 x = reinterpret_cast<const float4*>(Z + (size_t)row * D_)[t];
    float s  = x.x + x.y + x.z + x.w;
    float ss = x.x * x.x + x.y * x.y + x.z * x.z + x.w * x.w;
#pragma unroll
    for (int o = 16; o > 0; o >>= 1) {
        s  += __shfl_xor_sync(0xFFFFFFFFu, s, o);
        ss += __shfl_xor_sync(0xFFFFFFFFu, ss, o);
    }
    __shared__ float sh_s[8], sh_ss[8];
    int w = t >> 5, l = t & 31;
    if (l == 0) { sh_s[w] = s; sh_ss[w] = ss; }
    __syncthreads();
    if (w == 0) {
        s  = (l < 8) ? sh_s[l]  : 0.f;
        ss = (l < 8) ? sh_ss[l] : 0.f;
#pragma unroll
        for (int o = 4; o > 0; o >>= 1) {
            s  += __shfl_xor_sync(0xFFFFFFFFu, s, o);
            ss += __shfl_xor_sync(0xFFFFFFFFu, ss, o);
        }
        if (l == 0) { sh_s[0] = s; sh_ss[0] = ss; }
    }
    __syncthreads();
    float mean = sh_s[0] * (1.f / D_);
    float var  = sh_ss[0] * (1.f / D_) - mean * mean;
    float rstd = rsqrtf(var + 1e-5f);
    float4 gg = reinterpret_cast<const float4*>(g)[t];
    float4 bb = reinterpret_cast<const float4*>(b)[t];
    float4 y;
    y.x = (x.x - mean) * rstd * gg.x + bb.x;
    y.y = (x.y - mean) * rstd * gg.y + bb.y;
    y.z = (x.z - mean) * rstd * gg.z + bb.z;
    y.w = (x.w - mean) * rstd * gg.w + bb.w;
    reinterpret_cast<float4*>(out + (size_t)row * D_)[t] = y;
}

// ---------------- launch -------------------------------------------------------
extern "C" void kernel_launch(void* const* d_in, const int* in_sizes, int n_in,
                              void* d_out, int out_size)
{
    const float* x         = (const float*)d_in[0];
    const float* hidden    = (const float*)d_in[1];
    const float* rnn_start = (const float*)d_in[2];
    const float* Win       = (const float*)d_in[3];
    const float* bin_      = (const float*)d_in[4];
    const float* Wout      = (const float*)d_in[5];
    const float* bout      = (const float*)d_in[6];
    const float* W1        = (const float*)d_in[7];
    const float* b1        = (const float*)d_in[8];
    const float* W2        = (const float*)d_in[9];
    const float* b2        = (const float*)d_in[10];
    const float* ln_g      = (const float*)d_in[11];
    const float* ln_b      = (const float*)d_in[12];

    float* out        = (float*)d_out;
    float* hidden_out = out + (size_t)M_ * D_;

    float *buf0, *buf1, *buf2, *wT;
    cudaGetSymbolAddress((void**)&buf0, g_buf0);
    cudaGetSymbolAddress((void**)&buf1, g_buf1);
    cudaGetSymbolAddress((void**)&buf2, g_buf2);
    cudaGetSymbolAddress((void**)&wT,   g_wT);

    cudaFuncSetAttribute(tgemm_p<MODE_GATES, true>, cudaFuncAttributeMaxDynamicSharedMemorySize, GEMM_SMEM);
    cudaFuncSetAttribute(tgemm_p<MODE_BIAS, false>, cudaFuncAttributeMaxDynamicSharedMemorySize, GEMM_SMEM);
    cudaFuncSetAttribute(tgemm_p<MODE_GELU, false>, cudaFuncAttributeMaxDynamicSharedMemorySize, GEMM_SMEM);
    cudaFuncSetAttribute(tgemm_p<MODE_RESID, false>, cudaFuncAttributeMaxDynamicSharedMemorySize, GEMM_SMEM);
    cudaFuncSetAttribute(scan_pass2, cudaFuncAttributeMaxDynamicSharedMemorySize, 2 * NC * 128 * 4);

    int dev = 0, nsm = 148;
    cudaGetDevice(&dev);
    cudaDeviceGetAttribute(&nsm, cudaDevAttrMultiProcessorCount, dev);
    const int gridP = 2 * nsm;

    // 0: transpose, 1: cvt_x, 2: aim (no-op), 3: gates GEMM (profiled slot)
    transpose_tf32<<<dim3(32, 32, 5), dim3(32, 8)>>>(
        Win, Win + (size_t)K_ * D_, Wout, W1, W2, wT);
    cvt_x_kernel<<<(M_ * K_) / (256 * 4), 256>>>(x, buf2);
    aim_kernel<<<1, 32>>>();

    // v -> buf0 ; f -> buf1
    tgemm_p<MODE_GATES, true><<<gridP, 256, GEMM_SMEM>>>(buf2, wT, bin_, rnn_start, buf0, buf1);

    // chunked scan -> hs (tf32 bits) in buf2, hT -> hidden_out
    scan_pass1<<<(B_ * NC * D_) / 256, 256>>>(buf0, buf1);
    scan_pass2<<<32, 256, 2 * NC * 128 * 4>>>(hidden, hidden_out);
    scan_pass3<<<(B_ * NC * D_) / 256, 256>>>(buf0, buf1, buf2);

    // out = hs@Wout + bout -> buf0 (fp32) + buf1 (tf32 copy)
    tgemm_p<MODE_BIAS, false><<<gridP, 256, GEMM_SMEM>>>(buf2, wT + 2 * (size_t)K_ * D_, bout, nullptr, buf0, buf1);
    // x_ = gelu(out@W1 + b1) -> buf2 (tf32 bits)
    tgemm_p<MODE_GELU, false><<<gridP, 256, GEMM_SMEM>>>(buf1, wT + 3 * (size_t)K_ * D_, b1, nullptr, buf2, nullptr);
    // z = x_@W2 + b2 + out -> buf1 (fp32)
    tgemm_p<MODE_RESID, false><<<gridP, 256, GEMM_SMEM>>>(buf2, wT + 4 * (size_t)K_ * D_, b2, buf0, buf1, nullptr);
    // out = LN(z)
    ln_kernel<<<M_, 256>>>(buf1, ln_g, ln_b, out);
}

// round 10
// speedup vs baseline: 1.3323x; 1.3323x over previous
#include <cuda_runtime.h>
#include <math.h>
#include <stdint.h>

// Problem dims (fixed per setup_inputs)
#define B_   4
#define T_   4096
#define K_   1024          // Din == D == 1024
#define D_   1024
#define M_   (B_*T_)       // 16384

// ---------------- scratch (device globals; no allocations allowed) ---------
__device__ float g_buf0[(size_t)M_ * D_];   // 64 MB
__device__ float g_buf1[(size_t)M_ * D_];   // 64 MB
__device__ float g_buf2[(size_t)M_ * D_];   // 64 MB
__device__ float g_wT[(size_t)5 * K_ * D_]; // 20 MB transposed + tf32-rounded weights

#define CHUNK 32
#define NC    (T_/CHUNK)    // 128
__device__ float g_cA[B_*NC*D_];
__device__ float g_cP[B_*NC*D_];
__device__ float g_cC[B_*NC*D_];

// ---------------- helpers ----------------------------------------------------
__device__ __forceinline__ uint32_t cvt_tf32(float x) {
    uint32_t t; asm("cvt.rna.tf32.f32 %0, %1;" : "=r"(t) : "f"(x)); return t;
}
__device__ __forceinline__ uint32_t smem_u32(const void* p) {
    uint32_t a;
    asm("{ .reg .u64 t; cvta.to.shared.u64 t, %1; cvt.u32.u64 %0, t; }" : "=r"(a) : "l"(p));
    return a;
}
__device__ __forceinline__ void cp_async16(uint32_t saddr, const void* gptr) {
    asm volatile("cp.async.cg.shared.global [%0], [%1], 16;" :: "r"(saddr), "l"(gptr));
}
#define CP_COMMIT() asm volatile("cp.async.commit_group;" ::: "memory")
#define CP_WAIT1()  asm volatile("cp.async.wait_group 1;"  ::: "memory")
#define CP_WAIT0()  asm volatile("cp.async.wait_group 0;"  ::: "memory")

#define LDSM_X4(r0, r1, r2, r3, addr) \
    asm volatile("ldmatrix.sync.aligned.m8n8.x4.shared.b16 {%0,%1,%2,%3}, [%4];" \
                 : "=r"(r0), "=r"(r1), "=r"(r2), "=r"(r3) : "r"(addr))

__device__ __forceinline__ void mma_tf32(float c[4], const uint32_t a[4],
                                         uint32_t b0, uint32_t b1) {
    asm volatile(
        "mma.sync.aligned.m16n8k8.row.col.f32.tf32.tf32.f32 "
        "{%0,%1,%2,%3}, {%4,%5,%6,%7}, {%8,%9}, {%0,%1,%2,%3};"
        : "+f"(c[0]), "+f"(c[1]), "+f"(c[2]), "+f"(c[3])
        : "r"(a[0]), "r"(a[1]), "r"(a[2]), "r"(a[3]), "r"(b0), "r"(b1));
}

// ---------------- tf32 mma.sync GEMM core (round-7 verified schedule) ---------
// A [M,1024] tf32 bits; Bt [N,K] tf32 bits (N-major). CTA 128x128, BK=32,
// 3-stage cp.async; 8 warps (2M x 4N), warp 64x32; LDSM + register double-buffer.
// SMEM: XOR-swizzled 128B rows -> stage 16KB, 2 CTAs/SM.

#define BMm 128
#define BNm 128
#define BKm 32
#define STEPSm (K_/BKm)        // 32
#define STAGE_B 16384          // 128 rows * 128 bytes
#define NSTG 3
#define GEMM_SMEM (2*NSTG*STAGE_B)   // 98304 B

enum { MODE_TANH = 0, MODE_SIGF = 1, MODE_BIAS = 2, MODE_GELU = 3, MODE_RESID = 4 };

struct Frag { float acc[4][4][4]; };

__device__ __forceinline__ void gemm_mainloop(
    const float* __restrict__ Ab, const float* __restrict__ Bb,
    uint32_t sbase, int tid, int lane, int wm, int wn, Frag& fr)
{
    const uint32_t aB = sbase;
    const uint32_t bB = sbase + NSTG * STAGE_B;

    // cp.async mapping: 4 x 16B per matrix per stage per thread, swizzled cols
    const int r0 = tid >> 3;
    const int c4 = (tid & 7) << 2;
    const uint32_t soff0 = (uint32_t)(r0 << 7) + (((uint32_t)c4 << 2) ^ (((uint32_t)r0 & 7) << 4));

    // LDSM per-lane constants
    const int rr = lane & 7;
    const uint32_t swz   = (uint32_t)rr << 4;
    const uint32_t akoff = (uint32_t)((lane >> 4) & 1) << 4;
    const uint32_t bkoff = (uint32_t)((lane >> 3) & 1) << 4;
    const int a_row8 = (lane >> 3) & 1;
    const int b_n8   = (lane >> 4) & 1;
    uint32_t aoff[4];
#pragma unroll
    for (int mi = 0; mi < 4; mi++)
        aoff[mi] = (uint32_t)(wm * 64 + mi * 16 + a_row8 * 8 + rr) << 7;
    uint32_t boff[2];
#pragma unroll
    for (int j = 0; j < 2; j++)
        boff[j] = (uint32_t)(wn * 32 + j * 16 + b_n8 * 8 + rr) << 7;

#pragma unroll
    for (int mi = 0; mi < 4; mi++)
#pragma unroll
        for (int ni = 0; ni < 4; ni++)
#pragma unroll
            for (int q = 0; q < 4; q++) fr.acc[mi][ni][q] = 0.f;

    uint32_t af[2][4][4];   // double-buffered A fragments
    uint32_t bq[2][2][4];   // double-buffered B fragments

#define ISSUE_STAGE(S) do {                                                     \
        const int _k0 = (S) * BKm;                                              \
        const uint32_t _sa = aB + ((S) % NSTG) * STAGE_B + soff0;               \
        const uint32_t _sb = bB + ((S) % NSTG) * STAGE_B + soff0;               \
        _Pragma("unroll")                                                       \
        for (int j = 0; j < 4; j++) {                                           \
            const size_t go = (size_t)(r0 + 32 * j) * K_ + _k0 + c4;            \
            const uint32_t so = (uint32_t)(32 * j) << 7;                        \
            cp_async16(_sa + so, Ab + go);                                      \
            cp_async16(_sb + so, Bb + go);                                      \
        }                                                                       \
    } while (0)

#define LOAD_FRAGS(SLOT, SA, SB, KO) do {                                       \
        const uint32_t _ax = ((KO) + akoff) ^ swz;                              \
        const uint32_t _bx = ((KO) + bkoff) ^ swz;                              \
        _Pragma("unroll")                                                       \
        for (int mi = 0; mi < 4; mi++)                                          \
            LDSM_X4(af[SLOT][mi][0], af[SLOT][mi][1],                           \
                    af[SLOT][mi][2], af[SLOT][mi][3], (SA) + aoff[mi] + _ax);   \
        _Pragma("unroll")                                                       \
        for (int j = 0; j < 2; j++)                                             \
            LDSM_X4(bq[SLOT][j][0], bq[SLOT][j][1],                             \
                    bq[SLOT][j][2], bq[SLOT][j][3], (SB) + boff[j] + _bx);      \
    } while (0)

    ISSUE_STAGE(0); CP_COMMIT();
    ISSUE_STAGE(1); CP_COMMIT();
    CP_WAIT1();
    __syncthreads();

    uint32_t sa = aB, sb = bB;
    LOAD_FRAGS(0, sa, sb, 0u);

    for (int s = 0; s < STEPSm; s++) {
#pragma unroll
        for (int ks = 0; ks < 4; ks++) {
            if (ks < 3) {
                LOAD_FRAGS((ks + 1) & 1, sa, sb, (uint32_t)(ks + 1) * 32);
            } else if (s + 1 < STEPSm) {
                if (s + 2 < STEPSm) { ISSUE_STAGE(s + 2); CP_COMMIT(); CP_WAIT1(); }
                else                { CP_WAIT0(); }
                __syncthreads();
                sa = aB + ((s + 1) % NSTG) * STAGE_B;
                sb = bB + ((s + 1) % NSTG) * STAGE_B;
                LOAD_FRAGS(0, sa, sb, 0u);
            }
            const int p = ks & 1;
#pragma unroll
            for (int mi = 0; mi < 4; mi++)
#pragma unroll
                for (int ni = 0; ni < 4; ni++)
                    mma_tf32(fr.acc[mi][ni], af[p][mi],
                             bq[p][ni >> 1][(ni & 1) * 2],
                             bq[p][ni >> 1][(ni & 1) * 2 + 1]);
        }
    }
#undef ISSUE_STAGE
#undef LOAD_FRAGS
}

// ---- chain GEMMs (BIAS / GELU / RESID) --------------------------------------
template <int MODE>
__global__ __launch_bounds__(256, 2)
void tgemm(const float* __restrict__ A, const float* __restrict__ Bt,
           const float* __restrict__ bias, const float* __restrict__ extra,
           float* __restrict__ C, float* __restrict__ C2)
{
    extern __shared__ float smf[];
    const uint32_t sbase = smem_u32(smf);
    const int tid = threadIdx.x, lane = tid & 31, wid = tid >> 5;
    const int wm = wid >> 2, wn = wid & 3;
    const int bn = blockIdx.x, bm = blockIdx.y;

    Frag fr;
    gemm_mainloop(A + (size_t)bm * BMm * K_, Bt + (size_t)bn * BNm * K_,
                  sbase, tid, lane, wm, wn, fr);

    const int r_base = bm * BMm + wm * 64 + (lane >> 2);
    const int c_base = bn * BNm + wn * 32 + ((lane & 3) << 1);
#pragma unroll
    for (int mi = 0; mi < 4; mi++) {
        const int gr0 = r_base + mi * 16;
        const int gr1 = gr0 + 8;
#pragma unroll
        for (int ni = 0; ni < 4; ni++) {
            const int gc = c_base + ni * 8;
            float b0 = bias[gc], b1 = bias[gc + 1];
            float v0 = fr.acc[mi][ni][0] + b0;
            float v1 = fr.acc[mi][ni][1] + b1;
            float v2 = fr.acc[mi][ni][2] + b0;
            float v3 = fr.acc[mi][ni][3] + b1;
            if (MODE == MODE_GELU) {
                v0 = 0.5f * v0 * (1.f + erff(v0 * 0.70710678118654752f));
                v1 = 0.5f * v1 * (1.f + erff(v1 * 0.70710678118654752f));
                v2 = 0.5f * v2 * (1.f + erff(v2 * 0.70710678118654752f));
                v3 = 0.5f * v3 * (1.f + erff(v3 * 0.70710678118654752f));
                v0 = __uint_as_float(cvt_tf32(v0));
                v1 = __uint_as_float(cvt_tf32(v1));
                v2 = __uint_as_float(cvt_tf32(v2));
                v3 = __uint_as_float(cvt_tf32(v3));
            } else if (MODE == MODE_RESID) {
                const float2 e0 = *reinterpret_cast<const float2*>(extra + (size_t)gr0 * D_ + gc);
                const float2 e1 = *reinterpret_cast<const float2*>(extra + (size_t)gr1 * D_ + gc);
                v0 += e0.x; v1 += e0.y; v2 += e1.x; v3 += e1.y;
            }
            *reinterpret_cast<float2*>(C + (size_t)gr0 * D_ + gc) = make_float2(v0, v1);
            *reinterpret_cast<float2*>(C + (size_t)gr1 * D_ + gc) = make_float2(v2, v3);
            if (MODE == MODE_BIAS) {
                float t0 = __uint_as_float(cvt_tf32(v0));
                float t1 = __uint_as_float(cvt_tf32(v1));
                float t2 = __uint_as_float(cvt_tf32(v2));
                float t3 = __uint_as_float(cvt_tf32(v3));
                *reinterpret_cast<float2*>(C2 + (size_t)gr0 * D_ + gc) = make_float2(t0, t1);
                *reinterpret_cast<float2*>(C2 + (size_t)gr1 * D_ + gc) = make_float2(t2, t3);
            }
        }
    }
}

// ---- fused gate GEMMs: z=0 -> tanh -> Cv ; z=1 -> sigmoid*(1-rs) -> Cf ------
__global__ __launch_bounds__(256, 2)
void tgemm_gates(const float* __restrict__ A, const float* __restrict__ Wt,
                 const float* __restrict__ bin, const float* __restrict__ rnn_start,
                 float* __restrict__ Cv, float* __restrict__ Cf)
{
    extern __shared__ float smf[];
    const uint32_t sbase = smem_u32(smf);
    const int tid = threadIdx.x, lane = tid & 31, wid = tid >> 5;
    const int wm = wid >> 2, wn = wid & 3;
    const int bn = blockIdx.x, bm = blockIdx.y, z = blockIdx.z;

    const float* Bt   = Wt + (size_t)z * K_ * D_;
    const float* bias = bin + z * D_;

    Frag fr;
    gemm_mainloop(A + (size_t)bm * BMm * K_, Bt + (size_t)bn * BNm * K_,
                  sbase, tid, lane, wm, wn, fr);

    float* C = z ? Cf : Cv;
    const int r_base = bm * BMm + wm * 64 + (lane >> 2);
    const int c_base = bn * BNm + wn * 32 + ((lane & 3) << 1);
#pragma unroll
    for (int mi = 0; mi < 4; mi++) {
        const int gr0 = r_base + mi * 16;
        const int gr1 = gr0 + 8;
        float rs0 = 0.f, rs1 = 0.f;
        if (z) { rs0 = rnn_start[gr0]; rs1 = rnn_start[gr1]; }
#pragma unroll
        for (int ni = 0; ni < 4; ni++) {
            const int gc = c_base + ni * 8;
            float b0 = bias[gc], b1 = bias[gc + 1];
            float v0 = fr.acc[mi][ni][0] + b0;
            float v1 = fr.acc[mi][ni][1] + b1;
            float v2 = fr.acc[mi][ni][2] + b0;
            float v3 = fr.acc[mi][ni][3] + b1;
            if (z == 0) {
                v0 = tanhf(v0); v1 = tanhf(v1); v2 = tanhf(v2); v3 = tanhf(v3);
            } else {
                v0 = (1.f - rs0) / (1.f + expf(-v0));
                v1 = (1.f - rs0) / (1.f + expf(-v1));
                v2 = (1.f - rs1) / (1.f + expf(-v2));
                v3 = (1.f - rs1) / (1.f + expf(-v3));
            }
            *reinterpret_cast<float2*>(C + (size_t)gr0 * D_ + gc) = make_float2(v0, v1);
            *reinterpret_cast<float2*>(C + (size_t)gr1 * D_ + gc) = make_float2(v2, v3);
        }
    }
}

// ---------------- profiler-aim no-op (keeps gates GEMM at launch index 3) ----
__global__ void aim_kernel() { if (blockIdx.x == 0 && threadIdx.x == 0) g_cA[0] = 0.f; }

// ---------------- x -> tf32-rounded copy ------------------------------------
__global__ void cvt_x_kernel(const float* __restrict__ x, float* __restrict__ xt)
{
    int i = blockIdx.x * blockDim.x + threadIdx.x;
    float4 v = reinterpret_cast<const float4*>(x)[i];
    float4 o;
    o.x = __uint_as_float(cvt_tf32(v.x));
    o.y = __uint_as_float(cvt_tf32(v.y));
    o.z = __uint_as_float(cvt_tf32(v.z));
    o.w = __uint_as_float(cvt_tf32(v.w));
    reinterpret_cast<float4*>(xt)[i] = o;
}

// ---------------- weight transpose + tf32 rounding --------------------------
__global__ void transpose_tf32(const float* __restrict__ s0, const float* __restrict__ s1,
                               const float* __restrict__ s2, const float* __restrict__ s3,
                               const float* __restrict__ s4, float* __restrict__ dst)
{
    __shared__ float tile[32][33];
    const int z = blockIdx.z;
    const float* src = (z == 0) ? s0 : (z == 1) ? s1 : (z == 2) ? s2 : (z == 3) ? s3 : s4;
    float* d = dst + (size_t)z * K_ * D_;
    const int n0 = blockIdx.x * 32, k0 = blockIdx.y * 32;
    const int tx = threadIdx.x, ty = threadIdx.y;
#pragma unroll
    for (int r = 0; r < 32; r += 8)
        tile[ty + r][tx] = src[(size_t)(k0 + ty + r) * D_ + n0 + tx];
    __syncthreads();
#pragma unroll
    for (int r = 0; r < 32; r += 8) {
        uint32_t t = cvt_tf32(tile[tx][ty + r]);
        d[(size_t)(n0 + ty + r) * K_ + k0 + tx] = __uint_as_float(t);
    }
}

// ---------------- chunked scan (float4-vectorized over d) --------------------
__global__ void scan_pass1(const float4* __restrict__ V, const float4* __restrict__ F)
{
    int idx = blockIdx.x * blockDim.x + threadIdx.x;   // over B*NC*(D/4)
    int d4 = idx % (D_ / 4);
    int c  = (idx / (D_ / 4)) % NC;
    int b  = idx / ((D_ / 4) * NC);
    size_t base = ((size_t)b * T_ + (size_t)c * CHUNK) * (D_ / 4) + d4;
    float4 A = make_float4(1.f, 1.f, 1.f, 1.f);
    float4 h = make_float4(0.f, 0.f, 0.f, 0.f);
#pragma unroll 4
    for (int t = 0; t < CHUNK; t++) {
        float4 f = F[base + (size_t)t * (D_ / 4)];
        float4 v = V[base + (size_t)t * (D_ / 4)];
        A.x *= f.x; A.y *= f.y; A.z *= f.z; A.w *= f.w;
        h.x = f.x * h.x + (1.f - f.x) * v.x;
        h.y = f.y * h.y + (1.f - f.y) * v.y;
        h.z = f.z * h.z + (1.f - f.z) * v.z;
        h.w = f.w * h.w + (1.f - f.w) * v.w;
    }
    reinterpret_cast<float4*>(g_cA)[idx] = A;
    reinterpret_cast<float4*>(g_cP)[idx] = h;
}

__global__ void scan_pass2(const float* __restrict__ hidden, float* __restrict__ hT_out)
{
    extern __shared__ float sh[];
    float* sA = sh;
    float* sP = sh + NC * 128;
    const int blk = blockIdx.x;
    const int b   = blk >> 3;
    const int d0  = (blk & 7) * 128;
#pragma unroll 4
    for (int j = 0; j < 64; j++) {
        int i  = threadIdx.x + 256 * j;
        int c  = i >> 7, dd = i & 127;
        size_t g = ((size_t)b * NC + c) * D_ + d0 + dd;
        sA[i] = g_cA[g];
        sP[i] = g_cP[g];
    }
    __syncthreads();
    if (threadIdx.x < 128) {
        const int dd = threadIdx.x;
        float h = hidden[(size_t)b * D_ + d0 + dd];
        for (int c = 0; c < NC; c++) {
            g_cC[((size_t)b * NC + c) * D_ + d0 + dd] = h;
            h = sA[c * 128 + dd] * h + sP[c * 128 + dd];
        }
        hT_out[(size_t)b * D_ + d0 + dd] = h;
    }
}

__global__ void scan_pass3(const float4* __restrict__ V, const float4* __restrict__ F,
                           float4* __restrict__ HS)
{
    int idx = blockIdx.x * blockDim.x + threadIdx.x;   // over B*NC*(D/4)
    int d4 = idx % (D_ / 4);
    int c  = (idx / (D_ / 4)) % NC;
    int b  = idx / ((D_ / 4) * NC);
    size_t base = ((size_t)b * T_ + (size_t)c * CHUNK) * (D_ / 4) + d4;
    float4 h = reinterpret_cast<const float4*>(g_cC)[idx];
#pragma unroll 4
    for (int t = 0; t < CHUNK; t++) {
        float4 f = F[base + (size_t)t * (D_ / 4)];
        float4 v = V[base + (size_t)t * (D_ / 4)];
        h.x = f.x * h.x + (1.f - f.x) * v.x;
        h.y = f.y * h.y + (1.f - f.y) * v.y;
        h.z = f.z * h.z + (1.f - f.z) * v.z;
        h.w = f.w * h.w + (1.f - f.w) * v.w;
        float4 o;
        o.x = __uint_as_float(cvt_tf32(h.x));
        o.y = __uint_as_float(cvt_tf32(h.y));
        o.z = __uint_as_float(cvt_tf32(h.z));
        o.w = __uint_as_float(cvt_tf32(h.w));
        HS[base + (size_t)t * (D_ / 4)] = o;
    }
}

// ---------------- LayerNorm ---------------------------------------------------
__global__ __launch_bounds__(256)
void ln_kernel(const float* __restrict__ Z, const float* __restrict__ g,
               const float* __restrict__ b, float* __restrict__ out)
{
    int row = blockIdx.x;
    int t = threadIdx.x;
    float4 x = reinterpret_cast<const float4*>(Z + (size_t)row * D_)[t];
    float s  = x.x + x.y + x.z + x.w;
    float ss = x.x * x.x + x.y * x.y + x.z * x.z + x.w * x.w;
#pragma unroll
    for (int o = 16; o > 0; o >>= 1) {
        s  += __shfl_xor_sync(0xFFFFFFFFu, s, o);
        ss += __shfl_xor_sync(0xFFFFFFFFu, ss, o);
    }
    __shared__ float sh_s[8], sh_ss[8];
    int w = t >> 5, l = t & 31;
    if (l == 0) { sh_s[w] = s; sh_ss[w] = ss; }
    __syncthreads();
    if (w == 0) {
        s  = (l < 8) ? sh_s[l]  : 0.f;
        ss = (l < 8) ? sh_ss[l] : 0.f;
#pragma unroll
        for (int o = 4; o > 0; o >>= 1) {
            s  += __shfl_xor_sync(0xFFFFFFFFu, s, o);
            ss += __shfl_xor_sync(0xFFFFFFFFu, ss, o);
        }
        if (l == 0) { sh_s[0] = s; sh_ss[0] = ss; }
    }
    __syncthreads();
    float mean = sh_s[0] * (1.f / D_);
    float var  = sh_ss[0] * (1.f / D_) - mean * mean;
    float rstd = rsqrtf(var + 1e-5f);
    float4 gg = reinterpret_cast<const float4*>(g)[t];
    float4 bb = reinterpret_cast<const float4*>(b)[t];
    float4 y;
    y.x = (x.x - mean) * rstd * gg.x + bb.x;
    y.y = (x.y - mean) * rstd * gg.y + bb.y;
    y.z = (x.z - mean) * rstd * gg.z + bb.z;
    y.w = (x.w - mean) * rstd * gg.w + bb.w;
    reinterpret_cast<float4*>(out + (size_t)row * D_)[t] = y;
}

// ---------------- launch -------------------------------------------------------
extern "C" void kernel_launch(void* const* d_in, const int* in_sizes, int n_in,
                              void* d_out, int out_size)
{
    const float* x         = (const float*)d_in[0];
    const float* hidden    = (const float*)d_in[1];
    const float* rnn_start = (const float*)d_in[2];
    const float* Win       = (const float*)d_in[3];
    const float* bin_      = (const float*)d_in[4];
    const float* Wout      = (const float*)d_in[5];
    const float* bout      = (const float*)d_in[6];
    const float* W1        = (const float*)d_in[7];
    const float* b1        = (const float*)d_in[8];
    const float* W2        = (const float*)d_in[9];
    const float* b2        = (const float*)d_in[10];
    const float* ln_g      = (const float*)d_in[11];
    const float* ln_b      = (const float*)d_in[12];

    float* out        = (float*)d_out;
    float* hidden_out = out + (size_t)M_ * D_;

    float *buf0, *buf1, *buf2, *wT;
    cudaGetSymbolAddress((void**)&buf0, g_buf0);
    cudaGetSymbolAddress((void**)&buf1, g_buf1);
    cudaGetSymbolAddress((void**)&buf2, g_buf2);
    cudaGetSymbolAddress((void**)&wT,   g_wT);

    cudaFuncSetAttribute(tgemm_gates,       cudaFuncAttributeMaxDynamicSharedMemorySize, GEMM_SMEM);
    cudaFuncSetAttribute(tgemm<MODE_BIAS>,  cudaFuncAttributeMaxDynamicSharedMemorySize, GEMM_SMEM);
    cudaFuncSetAttribute(tgemm<MODE_GELU>,  cudaFuncAttributeMaxDynamicSharedMemorySize, GEMM_SMEM);
    cudaFuncSetAttribute(tgemm<MODE_RESID>, cudaFuncAttributeMaxDynamicSharedMemorySize, GEMM_SMEM);
    cudaFuncSetAttribute(scan_pass2, cudaFuncAttributeMaxDynamicSharedMemorySize, 2 * NC * 128 * 4);

    // 0: transpose, 1: cvt_x, 2: aim (no-op), 3: gates GEMM (profiled slot)
    transpose_tf32<<<dim3(32, 32, 5), dim3(32, 8)>>>(
        Win, Win + (size_t)K_ * D_, Wout, W1, W2, wT);
    cvt_x_kernel<<<(M_ * K_) / (256 * 4), 256>>>(x, buf2);
    aim_kernel<<<1, 32>>>();

    dim3 grid(D_ / BNm, M_ / BMm);        // (8, 128)
    dim3 grid_g(D_ / BNm, M_ / BMm, 2);   // both gates in one launch

    // v -> buf0 ; f -> buf1
    tgemm_gates<<<grid_g, 256, GEMM_SMEM>>>(buf2, wT, bin_, rnn_start, buf0, buf1);

    // chunked scan -> hs (tf32 bits) in buf2, hT -> hidden_out
    scan_pass1<<<(B_ * NC * (D_ / 4)) / 256, 256>>>((const float4*)buf0, (const float4*)buf1);
    scan_pass2<<<32, 256, 2 * NC * 128 * 4>>>(hidden, hidden_out);
    scan_pass3<<<(B_ * NC * (D_ / 4)) / 256, 256>>>((const float4*)buf0, (const float4*)buf1,
                                                    (float4*)buf2);

    // out = hs@Wout + bout -> buf0 (fp32) + buf1 (tf32 copy)
    tgemm<MODE_BIAS><<<grid, 256, GEMM_SMEM>>>(buf2, wT + 2 * (size_t)K_ * D_, bout, nullptr, buf0, buf1);
    // x_ = gelu(out@W1 + b1) -> buf2 (tf32 bits)
    tgemm<MODE_GELU><<<grid, 256, GEMM_SMEM>>>(buf1, wT + 3 * (size_t)K_ * D_, b1,   nullptr, buf2, nullptr);
    // z = x_@W2 + b2 + out -> buf1 (fp32)
    tgemm<MODE_RESID><<<grid, 256, GEMM_SMEM>>>(buf2, wT + 4 * (size_t)K_ * D_, b2,  buf0,    buf1, nullptr);
    // out = LN(z)
    ln_kernel<<<M_, 256>>>(buf1, ln_g, ln_b, out);
}

// round 11
// speedup vs baseline: 2.0138x; 1.5116x over previous
#include <cuda_runtime.h>
#include <cuda_fp16.h>
#include <math.h>
#include <stdint.h>

// Problem dims (fixed per setup_inputs)
#define B_   4
#define T_   4096
#define K_   1024          // Din == D == 1024
#define D_   1024
#define M_   (B_*T_)       // 16384

// ---------------- scratch (device globals; no allocations allowed) ---------
__device__ float  g_buf0[(size_t)M_ * D_];   // 64 MB fp32
__device__ float  g_buf1[(size_t)M_ * D_];   // 64 MB fp32
__device__ float  g_buf2[(size_t)M_ * D_];   // 64 MB (also reused as half)
__device__ __half g_wTh[(size_t)5 * K_ * D_]; // 10 MB transposed fp16 weights

#define CHUNK 32
#define NC    (T_/CHUNK)    // 128
__device__ float g_cA[B_*NC*D_];
__device__ float g_cP[B_*NC*D_];
__device__ float g_cC[B_*NC*D_];

// ---------------- helpers ----------------------------------------------------
__device__ __forceinline__ uint32_t smem_u32(const void* p) {
    uint32_t a;
    asm("{ .reg .u64 t; cvta.to.shared.u64 t, %1; cvt.u32.u64 %0, t; }" : "=r"(a) : "l"(p));
    return a;
}
__device__ __forceinline__ void cp_async16(uint32_t saddr, const void* gptr) {
    asm volatile("cp.async.cg.shared.global [%0], [%1], 16;" :: "r"(saddr), "l"(gptr));
}
#define CP_COMMIT() asm volatile("cp.async.commit_group;" ::: "memory")
#define CP_WAIT1()  asm volatile("cp.async.wait_group 1;"  ::: "memory")
#define CP_WAIT0()  asm volatile("cp.async.wait_group 0;"  ::: "memory")

#define LDSM_X4(r0, r1, r2, r3, addr) \
    asm volatile("ldmatrix.sync.aligned.m8n8.x4.shared.b16 {%0,%1,%2,%3}, [%4];" \
                 : "=r"(r0), "=r"(r1), "=r"(r2), "=r"(r3) : "r"(addr))

__device__ __forceinline__ void mma_f16(float c[4], const uint32_t a[4],
                                        uint32_t b0, uint32_t b1) {
    asm volatile(
        "mma.sync.aligned.m16n8k16.row.col.f32.f16.f16.f32 "
        "{%0,%1,%2,%3}, {%4,%5,%6,%7}, {%8,%9}, {%0,%1,%2,%3};"
        : "+f"(c[0]), "+f"(c[1]), "+f"(c[2]), "+f"(c[3])
        : "r"(a[0]), "r"(a[1]), "r"(a[2]), "r"(a[3]), "r"(b0), "r"(b1));
}

// ---------------- fp16 mma.sync GEMM core (round-7 verified schedule) ---------
// A [M,1024] fp16; Bt [N,K] fp16 (N-major). CTA 128x128, BK=32 (64B rows),
// 3-stage cp.async; 8 warps (2M x 4N), warp 64x32; LDSM + register double-buffer.
// SMEM: XOR-swizzled 64B rows (granule ^ ((row>>1)&3)) -> stage 8KB/matrix.

#define BMm 128
#define BNm 128
#define BKm 32
#define STEPSm (K_/BKm)        // 32
#define STAGE_B 8192           // 128 rows * 64 bytes
#define NSTG 3
#define GEMM_SMEM (2*NSTG*STAGE_B)   // 49152 B

enum { MODE_BIAS = 2, MODE_GELU = 3, MODE_RESID = 4 };

struct Frag { float acc[4][4][4]; };

__device__ __forceinline__ void gemm_mainloop(
    const __half* __restrict__ Ab, const __half* __restrict__ Bb,
    uint32_t sbase, int tid, int lane, int wm, int wn, Frag& fr)
{
    const uint32_t aB = sbase;
    const uint32_t bB = sbase + NSTG * STAGE_B;

    // cp.async mapping: 2 x 16B per matrix per stage per thread, swizzled granules
    const int r0 = tid >> 2;               // row for j=0 (j=1: +64)
    const int gc = tid & 3;                // 16B granule
    const uint32_t gce = (uint32_t)(gc ^ ((tid >> 3) & 3));
    const uint32_t soff0 = ((uint32_t)r0 << 6) + (gce << 4);

    // LDSM per-lane constants
    const int rr = lane & 7;
    const uint32_t swz   = (uint32_t)((rr >> 1) & 3);       // granule swizzle
    const uint32_t akblk = (uint32_t)((lane >> 4) & 1);     // A k 16B block
    const uint32_t bkblk = (uint32_t)((lane >> 3) & 1);     // B k 16B block
    const int a_row8 = (lane >> 3) & 1;
    const int b_n8   = (lane >> 4) & 1;
    uint32_t aoff[4];
#pragma unroll
    for (int mi = 0; mi < 4; mi++)
        aoff[mi] = (uint32_t)(wm * 64 + mi * 16 + a_row8 * 8 + rr) << 6;
    uint32_t boff[2];
#pragma unroll
    for (int j = 0; j < 2; j++)
        boff[j] = (uint32_t)(wn * 32 + j * 16 + b_n8 * 8 + rr) << 6;

#pragma unroll
    for (int mi = 0; mi < 4; mi++)
#pragma unroll
        for (int ni = 0; ni < 4; ni++)
#pragma unroll
            for (int q = 0; q < 4; q++) fr.acc[mi][ni][q] = 0.f;

    uint32_t af[2][4][4];   // double-buffered A fragments (slice-level)
    uint32_t bq[2][2][4];   // double-buffered B fragments

#define ISSUE_STAGE(S) do {                                                     \
        const int _k0 = (S) * BKm;                                              \
        const uint32_t _sa = aB + ((S) % NSTG) * STAGE_B + soff0;               \
        const uint32_t _sb = bB + ((S) % NSTG) * STAGE_B + soff0;               \
        _Pragma("unroll")                                                       \
        for (int j = 0; j < 2; j++) {                                           \
            const size_t go = (size_t)(r0 + 64 * j) * K_ + _k0 + gc * 8;        \
            const uint32_t so = (uint32_t)j << 12;  /* 64 rows * 64B */         \
            cp_async16(_sa + so, Ab + go);                                      \
            cp_async16(_sb + so, Bb + go);                                      \
        }                                                                       \
    } while (0)

#define LOAD_FRAGS(SLOT, SA, SB, SLICE) do {                                    \
        const uint32_t _ag = ((((uint32_t)(SLICE)) << 1) + akblk) ^ swz;        \
        const uint32_t _bg = ((((uint32_t)(SLICE)) << 1) + bkblk) ^ swz;        \
        _Pragma("unroll")                                                       \
        for (int mi = 0; mi < 4; mi++)                                          \
            LDSM_X4(af[SLOT][mi][0], af[SLOT][mi][1],                           \
                    af[SLOT][mi][2], af[SLOT][mi][3],                           \
                    (SA) + aoff[mi] + (_ag << 4));                              \
        _Pragma("unroll")                                                       \
        for (int j = 0; j < 2; j++)                                             \
            LDSM_X4(bq[SLOT][j][0], bq[SLOT][j][1],                             \
                    bq[SLOT][j][2], bq[SLOT][j][3],                             \
                    (SB) + boff[j] + (_bg << 4));                               \
    } while (0)

    ISSUE_STAGE(0); CP_COMMIT();
    ISSUE_STAGE(1); CP_COMMIT();
    CP_WAIT1();
    __syncthreads();

    uint32_t sa = aB, sb = bB;
    LOAD_FRAGS(0, sa, sb, 0);

    for (int s = 0; s < STEPSm; s++) {
#pragma unroll
        for (int ks = 0; ks < 2; ks++) {
            if (ks == 0) {
                LOAD_FRAGS(1, sa, sb, 1);
            } else if (s + 1 < STEPSm) {
                if (s + 2 < STEPSm) { ISSUE_STAGE(s + 2); CP_COMMIT(); CP_WAIT1(); }
                else                { CP_WAIT0(); }
                __syncthreads();
                sa = aB + ((s + 1) % NSTG) * STAGE_B;
                sb = bB + ((s + 1) % NSTG) * STAGE_B;
                LOAD_FRAGS(0, sa, sb, 0);
            }
            const int p = ks;
#pragma unroll
            for (int mi = 0; mi < 4; mi++)
#pragma unroll
                for (int ni = 0; ni < 4; ni++)
                    mma_f16(fr.acc[mi][ni], af[p][mi],
                            bq[p][ni >> 1][(ni & 1) * 2],
                            bq[p][ni >> 1][(ni & 1) * 2 + 1]);
        }
    }
#undef ISSUE_STAGE
#undef LOAD_FRAGS
}

// ---- chain GEMMs (BIAS / GELU / RESID) --------------------------------------
template <int MODE>
__global__ __launch_bounds__(256, 2)
void tgemm(const __half* __restrict__ A, const __half* __restrict__ Bt,
           const float* __restrict__ bias, const float* __restrict__ extra,
           float* __restrict__ C, __half* __restrict__ Ch)
{
    extern __shared__ float smf[];
    const uint32_t sbase = smem_u32(smf);
    const int tid = threadIdx.x, lane = tid & 31, wid = tid >> 5;
    const int wm = wid >> 2, wn = wid & 3;
    const int bn = blockIdx.x, bm = blockIdx.y;

    Frag fr;
    gemm_mainloop(A + (size_t)bm * BMm * K_, Bt + (size_t)bn * BNm * K_,
                  sbase, tid, lane, wm, wn, fr);

    const int r_base = bm * BMm + wm * 64 + (lane >> 2);
    const int c_base = bn * BNm + wn * 32 + ((lane & 3) << 1);
#pragma unroll
    for (int mi = 0; mi < 4; mi++) {
        const int gr0 = r_base + mi * 16;
        const int gr1 = gr0 + 8;
#pragma unroll
        for (int ni = 0; ni < 4; ni++) {
            const int gc = c_base + ni * 8;
            float b0 = bias[gc], b1 = bias[gc + 1];
            float v0 = fr.acc[mi][ni][0] + b0;
            float v1 = fr.acc[mi][ni][1] + b1;
            float v2 = fr.acc[mi][ni][2] + b0;
            float v3 = fr.acc[mi][ni][3] + b1;
            if (MODE == MODE_GELU) {
                v0 = 0.5f * v0 * (1.f + erff(v0 * 0.70710678118654752f));
                v1 = 0.5f * v1 * (1.f + erff(v1 * 0.70710678118654752f));
                v2 = 0.5f * v2 * (1.f + erff(v2 * 0.70710678118654752f));
                v3 = 0.5f * v3 * (1.f + erff(v3 * 0.70710678118654752f));
                // feeds next GEMM's A only -> fp16 store
                *reinterpret_cast<__half2*>(Ch + (size_t)gr0 * D_ + gc) = __floats2half2_rn(v0, v1);
                *reinterpret_cast<__half2*>(Ch + (size_t)gr1 * D_ + gc) = __floats2half2_rn(v2, v3);
            } else if (MODE == MODE_RESID) {
                const float2 e0 = *reinterpret_cast<const float2*>(extra + (size_t)gr0 * D_ + gc);
                const float2 e1 = *reinterpret_cast<const float2*>(extra + (size_t)gr1 * D_ + gc);
                v0 += e0.x; v1 += e0.y; v2 += e1.x; v3 += e1.y;
                *reinterpret_cast<float2*>(C + (size_t)gr0 * D_ + gc) = make_float2(v0, v1);
                *reinterpret_cast<float2*>(C + (size_t)gr1 * D_ + gc) = make_float2(v2, v3);
            } else {   // MODE_BIAS: fp32 out + fp16 copy
                *reinterpret_cast<float2*>(C + (size_t)gr0 * D_ + gc) = make_float2(v0, v1);
                *reinterpret_cast<float2*>(C + (size_t)gr1 * D_ + gc) = make_float2(v2, v3);
                *reinterpret_cast<__half2*>(Ch + (size_t)gr0 * D_ + gc) = __floats2half2_rn(v0, v1);
                *reinterpret_cast<__half2*>(Ch + (size_t)gr1 * D_ + gc) = __floats2half2_rn(v2, v3);
            }
        }
    }
}

// ---- fused gate GEMMs: z=0 -> tanh -> Cv ; z=1 -> sigmoid*(1-rs) -> Cf ------
__global__ __launch_bounds__(256, 2)
void tgemm_gates(const __half* __restrict__ A, const __half* __restrict__ Wt,
                 const float* __restrict__ bin, const float* __restrict__ rnn_start,
                 float* __restrict__ Cv, float* __restrict__ Cf)
{
    extern __shared__ float smf[];
    const uint32_t sbase = smem_u32(smf);
    const int tid = threadIdx.x, lane = tid & 31, wid = tid >> 5;
    const int wm = wid >> 2, wn = wid & 3;
    const int bn = blockIdx.x, bm = blockIdx.y, z = blockIdx.z;

    const __half* Bt  = Wt + (size_t)z * K_ * D_;
    const float* bias = bin + z * D_;

    Frag fr;
    gemm_mainloop(A + (size_t)bm * BMm * K_, Bt + (size_t)bn * BNm * K_,
                  sbase, tid, lane, wm, wn, fr);

    float* C = z ? Cf : Cv;
    const int r_base = bm * BMm + wm * 64 + (lane >> 2);
    const int c_base = bn * BNm + wn * 32 + ((lane & 3) << 1);
#pragma unroll
    for (int mi = 0; mi < 4; mi++) {
        const int gr0 = r_base + mi * 16;
        const int gr1 = gr0 + 8;
        float rs0 = 0.f, rs1 = 0.f;
        if (z) { rs0 = rnn_start[gr0]; rs1 = rnn_start[gr1]; }
#pragma unroll
        for (int ni = 0; ni < 4; ni++) {
            const int gc = c_base + ni * 8;
            float b0 = bias[gc], b1 = bias[gc + 1];
            float v0 = fr.acc[mi][ni][0] + b0;
            float v1 = fr.acc[mi][ni][1] + b1;
            float v2 = fr.acc[mi][ni][2] + b0;
            float v3 = fr.acc[mi][ni][3] + b1;
            if (z == 0) {
                v0 = tanhf(v0); v1 = tanhf(v1); v2 = tanhf(v2); v3 = tanhf(v3);
            } else {
                v0 = (1.f - rs0) / (1.f + expf(-v0));
                v1 = (1.f - rs0) / (1.f + expf(-v1));
                v2 = (1.f - rs1) / (1.f + expf(-v2));
                v3 = (1.f - rs1) / (1.f + expf(-v3));
            }
            *reinterpret_cast<float2*>(C + (size_t)gr0 * D_ + gc) = make_float2(v0, v1);
            *reinterpret_cast<float2*>(C + (size_t)gr1 * D_ + gc) = make_float2(v2, v3);
        }
    }
}

// ---------------- profiler-aim no-op (keeps gates GEMM at launch index 3) ----
__global__ void aim_kernel() { if (blockIdx.x == 0 && threadIdx.x == 0) g_cA[0] = 0.f; }

// ---------------- x -> fp16 copy ----------------------------------------------
__global__ void cvt_x_h(const float4* __restrict__ x, __half2* __restrict__ xh)
{
    int i = blockIdx.x * blockDim.x + threadIdx.x;
    float4 v = x[i];
    xh[i * 2 + 0] = __floats2half2_rn(v.x, v.y);
    xh[i * 2 + 1] = __floats2half2_rn(v.z, v.w);
}

// ---------------- weight transpose + fp16 -------------------------------------
__global__ void transpose_h(const float* __restrict__ s0, const float* __restrict__ s1,
                            const float* __restrict__ s2, const float* __restrict__ s3,
                            const float* __restrict__ s4, __half* __restrict__ dst)
{
    __shared__ float tile[32][33];
    const int z = blockIdx.z;
    const float* src = (z == 0) ? s0 : (z == 1) ? s1 : (z == 2) ? s2 : (z == 3) ? s3 : s4;
    __half* d = dst + (size_t)z * K_ * D_;
    const int n0 = blockIdx.x * 32, k0 = blockIdx.y * 32;
    const int tx = threadIdx.x, ty = threadIdx.y;
#pragma unroll
    for (int r = 0; r < 32; r += 8)
        tile[ty + r][tx] = src[(size_t)(k0 + ty + r) * D_ + n0 + tx];
    __syncthreads();
#pragma unroll
    for (int r = 0; r < 32; r += 8)
        d[(size_t)(n0 + ty + r) * K_ + k0 + tx] = __float2half_rn(tile[tx][ty + r]);
}

// ---------------- chunked scan (float4-vectorized over d) --------------------
__global__ void scan_pass1(const float4* __restrict__ V, const float4* __restrict__ F)
{
    int idx = blockIdx.x * blockDim.x + threadIdx.x;
    int d4 = idx % (D_ / 4);
    int c  = (idx / (D_ / 4)) % NC;
    int b  = idx / ((D_ / 4) * NC);
    size_t base = ((size_t)b * T_ + (size_t)c * CHUNK) * (D_ / 4) + d4;
    float4 A = make_float4(1.f, 1.f, 1.f, 1.f);
    float4 h = make_float4(0.f, 0.f, 0.f, 0.f);
#pragma unroll 4
    for (int t = 0; t < CHUNK; t++) {
        float4 f = F[base + (size_t)t * (D_ / 4)];
        float4 v = V[base + (size_t)t * (D_ / 4)];
        A.x *= f.x; A.y *= f.y; A.z *= f.z; A.w *= f.w;
        h.x = f.x * h.x + (1.f - f.x) * v.x;
        h.y = f.y * h.y + (1.f - f.y) * v.y;
        h.z = f.z * h.z + (1.f - f.z) * v.z;
        h.w = f.w * h.w + (1.f - f.w) * v.w;
    }
    reinterpret_cast<float4*>(g_cA)[idx] = A;
    reinterpret_cast<float4*>(g_cP)[idx] = h;
}

__global__ void scan_pass2(const float* __restrict__ hidden, float* __restrict__ hT_out)
{
    extern __shared__ float sh[];
    float* sA = sh;
    float* sP = sh + NC * 128;
    const int blk = blockIdx.x;
    const int b   = blk >> 3;
    const int d0  = (blk & 7) * 128;
#pragma unroll 4
    for (int j = 0; j < 64; j++) {
        int i  = threadIdx.x + 256 * j;
        int c  = i >> 7, dd = i & 127;
        size_t g = ((size_t)b * NC + c) * D_ + d0 + dd;
        sA[i] = g_cA[g];
        sP[i] = g_cP[g];
    }
    __syncthreads();
    if (threadIdx.x < 128) {
        const int dd = threadIdx.x;
        float h = hidden[(size_t)b * D_ + d0 + dd];
        for (int c = 0; c < NC; c++) {
            g_cC[((size_t)b * NC + c) * D_ + d0 + dd] = h;
            h = sA[c * 128 + dd] * h + sP[c * 128 + dd];
        }
        hT_out[(size_t)b * D_ + d0 + dd] = h;
    }
}

// emits hs as fp16 (consumed only as GEMM3's A operand)
__global__ void scan_pass3(const float4* __restrict__ V, const float4* __restrict__ F,
                           __half2* __restrict__ HS)
{
    int idx = blockIdx.x * blockDim.x + threadIdx.x;
    int d4 = idx % (D_ / 4);
    int c  = (idx / (D_ / 4)) % NC;
    int b  = idx / ((D_ / 4) * NC);
    size_t base = ((size_t)b * T_ + (size_t)c * CHUNK) * (D_ / 4) + d4;
    float4 h = reinterpret_cast<const float4*>(g_cC)[idx];
#pragma unroll 4
    for (int t = 0; t < CHUNK; t++) {
        float4 f = F[base + (size_t)t * (D_ / 4)];
        float4 v = V[base + (size_t)t * (D_ / 4)];
        h.x = f.x * h.x + (1.f - f.x) * v.x;
        h.y = f.y * h.y + (1.f - f.y) * v.y;
        h.z = f.z * h.z + (1.f - f.z) * v.z;
        h.w = f.w * h.w + (1.f - f.w) * v.w;
        size_t o = (base + (size_t)t * (D_ / 4)) * 2;
        HS[o + 0] = __floats2half2_rn(h.x, h.y);
        HS[o + 1] = __floats2half2_rn(h.z, h.w);
    }
}

// ---------------- LayerNorm ---------------------------------------------------
__global__ __launch_bounds__(256)
void ln_kernel(const float* __restrict__ Z, const float* __restrict__ g,
               const float* __restrict__ b, float* __restrict__ out)
{
    int row = blockIdx.x;
    int t = threadIdx.x;
    float4 x = reinterpret_cast<const float4*>(Z + (size_t)row * D_)[t];
    float s  = x.x + x.y + x.z + x.w;
    float ss = x.x * x.x + x.y * x.y + x.z * x.z + x.w * x.w;
#pragma unroll
    for (int o = 16; o > 0; o >>= 1) {
        s  += __shfl_xor_sync(0xFFFFFFFFu, s, o);
        ss += __shfl_xor_sync(0xFFFFFFFFu, ss, o);
    }
    __shared__ float sh_s[8], sh_ss[8];
    int w = t >> 5, l = t & 31;
    if (l == 0) { sh_s[w] = s; sh_ss[w] = ss; }
    __syncthreads();
    if (w == 0) {
        s  = (l < 8) ? sh_s[l]  : 0.f;
        ss = (l < 8) ? sh_ss[l] : 0.f;
#pragma unroll
        for (int o = 4; o > 0; o >>= 1) {
            s  += __shfl_xor_sync(0xFFFFFFFFu, s, o);
            ss += __shfl_xor_sync(0xFFFFFFFFu, ss, o);
        }
        if (l == 0) { sh_s[0] = s; sh_ss[0] = ss; }
    }
    __syncthreads();
    float mean = sh_s[0] * (1.f / D_);
    float var  = sh_ss[0] * (1.f / D_) - mean * mean;
    float rstd = rsqrtf(var + 1e-5f);
    float4 gg = reinterpret_cast<const float4*>(g)[t];
    float4 bb = reinterpret_cast<const float4*>(b)[t];
    float4 y;
    y.x = (x.x - mean) * rstd * gg.x + bb.x;
    y.y = (x.y - mean) * rstd * gg.y + bb.y;
    y.z = (x.z - mean) * rstd * gg.z + bb.z;
    y.w = (x.w - mean) * rstd * gg.w + bb.w;
    reinterpret_cast<float4*>(out + (size_t)row * D_)[t] = y;
}

// ---------------- launch -------------------------------------------------------
extern "C" void kernel_launch(void* const* d_in, const int* in_sizes, int n_in,
                              void* d_out, int out_size)
{
    const float* x         = (const float*)d_in[0];
    const float* hidden    = (const float*)d_in[1];
    const float* rnn_start = (const float*)d_in[2];
    const float* Win       = (const float*)d_in[3];
    const float* bin_      = (const float*)d_in[4];
    const float* Wout      = (const float*)d_in[5];
    const float* bout      = (const float*)d_in[6];
    const float* W1        = (const float*)d_in[7];
    const float* b1        = (const float*)d_in[8];
    const float* W2        = (const float*)d_in[9];
    const float* b2        = (const float*)d_in[10];
    const float* ln_g      = (const float*)d_in[11];
    const float* ln_b      = (const float*)d_in[12];

    float* out        = (float*)d_out;
    float* hidden_out = out + (size_t)M_ * D_;

    float *buf0, *buf1, *buf2;
    __half* wTh;
    cudaGetSymbolAddress((void**)&buf0, g_buf0);
    cudaGetSymbolAddress((void**)&buf1, g_buf1);
    cudaGetSymbolAddress((void**)&buf2, g_buf2);
    cudaGetSymbolAddress((void**)&wTh,  g_wTh);

    cudaFuncSetAttribute(tgemm_gates,       cudaFuncAttributeMaxDynamicSharedMemorySize, GEMM_SMEM);
    cudaFuncSetAttribute(tgemm<MODE_BIAS>,  cudaFuncAttributeMaxDynamicSharedMemorySize, GEMM_SMEM);
    cudaFuncSetAttribute(tgemm<MODE_GELU>,  cudaFuncAttributeMaxDynamicSharedMemorySize, GEMM_SMEM);
    cudaFuncSetAttribute(tgemm<MODE_RESID>, cudaFuncAttributeMaxDynamicSharedMemorySize, GEMM_SMEM);
    cudaFuncSetAttribute(scan_pass2, cudaFuncAttributeMaxDynamicSharedMemorySize, 2 * NC * 128 * 4);

    __half* xh  = (__half*)buf2;   // fp16 x (32 MB of buf2)
    __half* hsh = (__half*)buf2;   // fp16 hs (reuses buf2 after xh is dead)
    __half* oh  = (__half*)buf1;   // fp16 out copy (after f is dead)
    __half* x_h = (__half*)buf2;   // fp16 gelu output (after hs is dead)

    // 0: transpose, 1: cvt_x, 2: aim (no-op), 3: gates GEMM (profiled slot)
    transpose_h<<<dim3(32, 32, 5), dim3(32, 8)>>>(
        Win, Win + (size_t)K_ * D_, Wout, W1, W2, wTh);
    cvt_x_h<<<(M_ * K_) / (256 * 4), 256>>>((const float4*)x, (__half2*)xh);
    aim_kernel<<<1, 32>>>();

    dim3 grid(D_ / BNm, M_ / BMm);        // (8, 128)
    dim3 grid_g(D_ / BNm, M_ / BMm, 2);   // both gates in one launch

    // v -> buf0 ; f -> buf1
    tgemm_gates<<<grid_g, 256, GEMM_SMEM>>>(xh, wTh, bin_, rnn_start, buf0, buf1);

    // chunked scan -> hs (fp16) into buf2, hT -> hidden_out
    scan_pass1<<<(B_ * NC * (D_ / 4)) / 256, 256>>>((const float4*)buf0, (const float4*)buf1);
    scan_pass2<<<32, 256, 2 * NC * 128 * 4>>>(hidden, hidden_out);
    scan_pass3<<<(B_ * NC * (D_ / 4)) / 256, 256>>>((const float4*)buf0, (const float4*)buf1,
                                                    (__half2*)hsh);

    // out = hs@Wout + bout -> buf0 (fp32) + oh (fp16 copy)
    tgemm<MODE_BIAS><<<grid, 256, GEMM_SMEM>>>(hsh, wTh + 2 * (size_t)K_ * D_, bout, nullptr, buf0, oh);
    // x_ = gelu(out@W1 + b1) -> x_h (fp16)
    tgemm<MODE_GELU><<<grid, 256, GEMM_SMEM>>>(oh, wTh + 3 * (size_t)K_ * D_, b1, nullptr, nullptr, x_h);
    // z = x_@W2 + b2 + out -> buf1 (fp32)
    tgemm<MODE_RESID><<<grid, 256, GEMM_SMEM>>>(x_h, wTh + 4 * (size_t)K_ * D_, b2, buf0, buf1, nullptr);
    // out = LN(z)
    ln_kernel<<<M_, 256>>>(buf1, ln_g, ln_b, out);
}

// round 12
// speedup vs baseline: 2.1013x; 1.0434x over previous
#include <cuda_runtime.h>
#include <cuda_fp16.h>
#include <math.h>
#include <stdint.h>

// Problem dims (fixed per setup_inputs)
#define B_   4
#define T_   4096
#define K_   1024          // Din == D == 1024
#define D_   1024
#define M_   (B_*T_)       // 16384

// ---------------- scratch (device globals; no allocations allowed) ---------
__device__ float  g_buf0[(size_t)M_ * D_];   // 64 MB fp32
__device__ float  g_buf1[(size_t)M_ * D_];   // 64 MB fp32 (also reused as half)
__device__ float  g_buf2[(size_t)M_ * D_];   // 64 MB (also reused as half)
__device__ __half g_wTh[(size_t)5 * K_ * D_]; // 10 MB transposed fp16 weights

#define CHUNK 32
#define NC    (T_/CHUNK)    // 128
__device__ float g_cA[B_*NC*D_];
__device__ float g_cP[B_*NC*D_];
__device__ float g_cC[B_*NC*D_];

// ---------------- helpers ----------------------------------------------------
__device__ __forceinline__ uint32_t smem_u32(const void* p) {
    uint32_t a;
    asm("{ .reg .u64 t; cvta.to.shared.u64 t, %1; cvt.u32.u64 %0, t; }" : "=r"(a) : "l"(p));
    return a;
}
__device__ __forceinline__ void cp_async16(uint32_t saddr, const void* gptr) {
    asm volatile("cp.async.cg.shared.global [%0], [%1], 16;" :: "r"(saddr), "l"(gptr));
}
#define CP_COMMIT() asm volatile("cp.async.commit_group;" ::: "memory")
#define CP_WAIT1()  asm volatile("cp.async.wait_group 1;"  ::: "memory")
#define CP_WAIT0()  asm volatile("cp.async.wait_group 0;"  ::: "memory")

#define LDSM_X4(r0, r1, r2, r3, addr) \
    asm volatile("ldmatrix.sync.aligned.m8n8.x4.shared.b16 {%0,%1,%2,%3}, [%4];" \
                 : "=r"(r0), "=r"(r1), "=r"(r2), "=r"(r3) : "r"(addr))

__device__ __forceinline__ void mma_f16(float c[4], const uint32_t a[4],
                                        uint32_t b0, uint32_t b1) {
    asm volatile(
        "mma.sync.aligned.m16n8k16.row.col.f32.f16.f16.f32 "
        "{%0,%1,%2,%3}, {%4,%5,%6,%7}, {%8,%9}, {%0,%1,%2,%3};"
        : "+f"(c[0]), "+f"(c[1]), "+f"(c[2]), "+f"(c[3])
        : "r"(a[0]), "r"(a[1]), "r"(a[2]), "r"(a[3]), "r"(b0), "r"(b1));
}

// ---------------- fp16 mma.sync GEMM core (round-7 schedule, BK=64) ----------
// A [M,1024] fp16; Bt [N,K] fp16 (N-major). CTA 128x128, BK=64 (128B rows),
// 3-stage cp.async; 8 warps (2M x 4N), warp 64x32; LDSM + register double-buffer.
// SMEM: XOR-swizzled 128B rows -> stage 16KB/matrix, 2 CTAs/SM (96KB/CTA).

#define BMm 128
#define BNm 128
#define BKm 64
#define STEPSm (K_/BKm)        // 16
#define STAGE_B 16384          // 128 rows * 128 bytes
#define NSTG 3
#define GEMM_SMEM (2*NSTG*STAGE_B)   // 98304 B

enum { MODE_BIAS = 2, MODE_GELU = 3, MODE_RESID = 4 };

struct Frag { float acc[4][4][4]; };

__device__ __forceinline__ void gemm_mainloop(
    const __half* __restrict__ Ab, const __half* __restrict__ Bb,
    uint32_t sbase, int tid, int lane, int wm, int wn, Frag& fr)
{
    const uint32_t aB = sbase;
    const uint32_t bB = sbase + NSTG * STAGE_B;

    // cp.async mapping: 4 x 16B per matrix per stage per thread, swizzled cols
    const int r0 = tid >> 3;               // row (+32*j)
    const int g8 = (tid & 7) * 8;          // col in halves (16B granule)
    const uint32_t soff0 = ((uint32_t)r0 << 7)
                         + ((((uint32_t)tid & 7) << 4) ^ (((uint32_t)r0 & 7) << 4));

    // LDSM per-lane constants (fp16 mapping verified in round 11)
    const int rr = lane & 7;
    const uint32_t swz   = (uint32_t)rr << 4;
    const uint32_t akoff = (uint32_t)((lane >> 4) & 1) << 4;   // A k 16B block
    const uint32_t bkoff = (uint32_t)((lane >> 3) & 1) << 4;   // B k 16B block
    const int a_row8 = (lane >> 3) & 1;
    const int b_n8   = (lane >> 4) & 1;
    uint32_t aoff[4];
#pragma unroll
    for (int mi = 0; mi < 4; mi++)
        aoff[mi] = (uint32_t)(wm * 64 + mi * 16 + a_row8 * 8 + rr) << 7;
    uint32_t boff[2];
#pragma unroll
    for (int j = 0; j < 2; j++)
        boff[j] = (uint32_t)(wn * 32 + j * 16 + b_n8 * 8 + rr) << 7;

#pragma unroll
    for (int mi = 0; mi < 4; mi++)
#pragma unroll
        for (int ni = 0; ni < 4; ni++)
#pragma unroll
            for (int q = 0; q < 4; q++) fr.acc[mi][ni][q] = 0.f;

    uint32_t af[2][4][4];   // double-buffered A fragments
    uint32_t bq[2][2][4];   // double-buffered B fragments

#define ISSUE_STAGE(S) do {                                                     \
        const int _k0 = (S) * BKm;                                              \
        const uint32_t _sa = aB + ((S) % NSTG) * STAGE_B + soff0;               \
        const uint32_t _sb = bB + ((S) % NSTG) * STAGE_B + soff0;               \
        _Pragma("unroll")                                                       \
        for (int j = 0; j < 4; j++) {                                           \
            const size_t go = (size_t)(r0 + 32 * j) * K_ + _k0 + g8;            \
            const uint32_t so = (uint32_t)(32 * j) << 7;                        \
            cp_async16(_sa + so, Ab + go);                                      \
            cp_async16(_sb + so, Bb + go);                                      \
        }                                                                       \
    } while (0)

#define LOAD_FRAGS(SLOT, SA, SB, KO) do {                                       \
        const uint32_t _ax = ((KO) + akoff) ^ swz;                              \
        const uint32_t _bx = ((KO) + bkoff) ^ swz;                              \
        _Pragma("unroll")                                                       \
        for (int mi = 0; mi < 4; mi++)                                          \
            LDSM_X4(af[SLOT][mi][0], af[SLOT][mi][1],                           \
                    af[SLOT][mi][2], af[SLOT][mi][3], (SA) + aoff[mi] + _ax);   \
        _Pragma("unroll")                                                       \
        for (int j = 0; j < 2; j++)                                             \
            LDSM_X4(bq[SLOT][j][0], bq[SLOT][j][1],                             \
                    bq[SLOT][j][2], bq[SLOT][j][3], (SB) + boff[j] + _bx);      \
    } while (0)

    ISSUE_STAGE(0); CP_COMMIT();
    ISSUE_STAGE(1); CP_COMMIT();
    CP_WAIT1();
    __syncthreads();

    uint32_t sa = aB, sb = bB;
    LOAD_FRAGS(0, sa, sb, 0u);

    for (int s = 0; s < STEPSm; s++) {
#pragma unroll
        for (int ks = 0; ks < 4; ks++) {
            if (ks < 3) {
                LOAD_FRAGS((ks + 1) & 1, sa, sb, (uint32_t)(ks + 1) * 32);
            } else if (s + 1 < STEPSm) {
                if (s + 2 < STEPSm) { ISSUE_STAGE(s + 2); CP_COMMIT(); CP_WAIT1(); }
                else                { CP_WAIT0(); }
                __syncthreads();
                sa = aB + ((s + 1) % NSTG) * STAGE_B;
                sb = bB + ((s + 1) % NSTG) * STAGE_B;
                LOAD_FRAGS(0, sa, sb, 0u);
            }
            const int p = ks & 1;
#pragma unroll
            for (int mi = 0; mi < 4; mi++)
#pragma unroll
                for (int ni = 0; ni < 4; ni++)
                    mma_f16(fr.acc[mi][ni], af[p][mi],
                            bq[p][ni >> 1][(ni & 1) * 2],
                            bq[p][ni >> 1][(ni & 1) * 2 + 1]);
        }
    }
#undef ISSUE_STAGE
#undef LOAD_FRAGS
}

// ---- chain GEMMs (BIAS / GELU / RESID) --------------------------------------
template <int MODE>
__global__ __launch_bounds__(256, 2)
void tgemm(const __half* __restrict__ A, const __half* __restrict__ Bt,
           const float* __restrict__ bias, const float* __restrict__ extra,
           float* __restrict__ C, __half* __restrict__ Ch)
{
    extern __shared__ float smf[];
    const uint32_t sbase = smem_u32(smf);
    const int tid = threadIdx.x, lane = tid & 31, wid = tid >> 5;
    const int wm = wid >> 2, wn = wid & 3;
    const int bn = blockIdx.x, bm = blockIdx.y;

    Frag fr;
    gemm_mainloop(A + (size_t)bm * BMm * K_, Bt + (size_t)bn * BNm * K_,
                  sbase, tid, lane, wm, wn, fr);

    const int r_base = bm * BMm + wm * 64 + (lane >> 2);
    const int c_base = bn * BNm + wn * 32 + ((lane & 3) << 1);
#pragma unroll
    for (int mi = 0; mi < 4; mi++) {
        const int gr0 = r_base + mi * 16;
        const int gr1 = gr0 + 8;
#pragma unroll
        for (int ni = 0; ni < 4; ni++) {
            const int gc = c_base + ni * 8;
            float b0 = bias[gc], b1 = bias[gc + 1];
            float v0 = fr.acc[mi][ni][0] + b0;
            float v1 = fr.acc[mi][ni][1] + b1;
            float v2 = fr.acc[mi][ni][2] + b0;
            float v3 = fr.acc[mi][ni][3] + b1;
            if (MODE == MODE_GELU) {
                v0 = 0.5f * v0 * (1.f + erff(v0 * 0.70710678118654752f));
                v1 = 0.5f * v1 * (1.f + erff(v1 * 0.70710678118654752f));
                v2 = 0.5f * v2 * (1.f + erff(v2 * 0.70710678118654752f));
                v3 = 0.5f * v3 * (1.f + erff(v3 * 0.70710678118654752f));
                *reinterpret_cast<__half2*>(Ch + (size_t)gr0 * D_ + gc) = __floats2half2_rn(v0, v1);
                *reinterpret_cast<__half2*>(Ch + (size_t)gr1 * D_ + gc) = __floats2half2_rn(v2, v3);
            } else if (MODE == MODE_RESID) {
                const float2 e0 = *reinterpret_cast<const float2*>(extra + (size_t)gr0 * D_ + gc);
                const float2 e1 = *reinterpret_cast<const float2*>(extra + (size_t)gr1 * D_ + gc);
                v0 += e0.x; v1 += e0.y; v2 += e1.x; v3 += e1.y;
                *reinterpret_cast<float2*>(C + (size_t)gr0 * D_ + gc) = make_float2(v0, v1);
                *reinterpret_cast<float2*>(C + (size_t)gr1 * D_ + gc) = make_float2(v2, v3);
            } else {   // MODE_BIAS: fp32 out + fp16 copy
                *reinterpret_cast<float2*>(C + (size_t)gr0 * D_ + gc) = make_float2(v0, v1);
                *reinterpret_cast<float2*>(C + (size_t)gr1 * D_ + gc) = make_float2(v2, v3);
                *reinterpret_cast<__half2*>(Ch + (size_t)gr0 * D_ + gc) = __floats2half2_rn(v0, v1);
                *reinterpret_cast<__half2*>(Ch + (size_t)gr1 * D_ + gc) = __floats2half2_rn(v2, v3);
            }
        }
    }
}

// ---- fused gate GEMMs: z=0 -> tanh -> Cv ; z=1 -> sigmoid*(1-rs) -> Cf ------
__global__ __launch_bounds__(256, 2)
void tgemm_gates(const __half* __restrict__ A, const __half* __restrict__ Wt,
                 const float* __restrict__ bin, const float* __restrict__ rnn_start,
                 float* __restrict__ Cv, float* __restrict__ Cf)
{
    extern __shared__ float smf[];
    const uint32_t sbase = smem_u32(smf);
    const int tid = threadIdx.x, lane = tid & 31, wid = tid >> 5;
    const int wm = wid >> 2, wn = wid & 3;
    const int bn = blockIdx.x, bm = blockIdx.y, z = blockIdx.z;

    const __half* Bt  = Wt + (size_t)z * K_ * D_;
    const float* bias = bin + z * D_;

    Frag fr;
    gemm_mainloop(A + (size_t)bm * BMm * K_, Bt + (size_t)bn * BNm * K_,
                  sbase, tid, lane, wm, wn, fr);

    float* C = z ? Cf : Cv;
    const int r_base = bm * BMm + wm * 64 + (lane >> 2);
    const int c_base = bn * BNm + wn * 32 + ((lane & 3) << 1);
#pragma unroll
    for (int mi = 0; mi < 4; mi++) {
        const int gr0 = r_base + mi * 16;
        const int gr1 = gr0 + 8;
        float rs0 = 0.f, rs1 = 0.f;
        if (z) { rs0 = rnn_start[gr0]; rs1 = rnn_start[gr1]; }
#pragma unroll
        for (int ni = 0; ni < 4; ni++) {
            const int gc = c_base + ni * 8;
            float b0 = bias[gc], b1 = bias[gc + 1];
            float v0 = fr.acc[mi][ni][0] + b0;
            float v1 = fr.acc[mi][ni][1] + b1;
            float v2 = fr.acc[mi][ni][2] + b0;
            float v3 = fr.acc[mi][ni][3] + b1;
            if (z == 0) {
                v0 = tanhf(v0); v1 = tanhf(v1); v2 = tanhf(v2); v3 = tanhf(v3);
            } else {
                v0 = (1.f - rs0) / (1.f + expf(-v0));
                v1 = (1.f - rs0) / (1.f + expf(-v1));
                v2 = (1.f - rs1) / (1.f + expf(-v2));
                v3 = (1.f - rs1) / (1.f + expf(-v3));
            }
            *reinterpret_cast<float2*>(C + (size_t)gr0 * D_ + gc) = make_float2(v0, v1);
            *reinterpret_cast<float2*>(C + (size_t)gr1 * D_ + gc) = make_float2(v2, v3);
        }
    }
}

// ---------------- profiler-aim no-op (keeps gates GEMM at launch index 3) ----
__global__ void aim_kernel() { if (blockIdx.x == 0 && threadIdx.x == 0) g_cA[0] = 0.f; }

// ---------------- x -> fp16 copy ----------------------------------------------
__global__ void cvt_x_h(const float4* __restrict__ x, __half2* __restrict__ xh)
{
    int i = blockIdx.x * blockDim.x + threadIdx.x;
    float4 v = x[i];
    xh[i * 2 + 0] = __floats2half2_rn(v.x, v.y);
    xh[i * 2 + 1] = __floats2half2_rn(v.z, v.w);
}

// ---------------- weight transpose + fp16 -------------------------------------
__global__ void transpose_h(const float* __restrict__ s0, const float* __restrict__ s1,
                            const float* __restrict__ s2, const float* __restrict__ s3,
                            const float* __restrict__ s4, __half* __restrict__ dst)
{
    __shared__ float tile[32][33];
    const int z = blockIdx.z;
    const float* src = (z == 0) ? s0 : (z == 1) ? s1 : (z == 2) ? s2 : (z == 3) ? s3 : s4;
    __half* d = dst + (size_t)z * K_ * D_;
    const int n0 = blockIdx.x * 32, k0 = blockIdx.y * 32;
    const int tx = threadIdx.x, ty = threadIdx.y;
#pragma unroll
    for (int r = 0; r < 32; r += 8)
        tile[ty + r][tx] = src[(size_t)(k0 + ty + r) * D_ + n0 + tx];
    __syncthreads();
#pragma unroll
    for (int r = 0; r < 32; r += 8)
        d[(size_t)(n0 + ty + r) * K_ + k0 + tx] = __float2half_rn(tile[tx][ty + r]);
}

// ---------------- chunked scan (float4-vectorized over d) --------------------
__global__ void scan_pass1(const float4* __restrict__ V, const float4* __restrict__ F)
{
    int idx = blockIdx.x * blockDim.x + threadIdx.x;
    int d4 = idx % (D_ / 4);
    int c  = (idx / (D_ / 4)) % NC;
    int b  = idx / ((D_ / 4) * NC);
    size_t base = ((size_t)b * T_ + (size_t)c * CHUNK) * (D_ / 4) + d4;
    float4 A = make_float4(1.f, 1.f, 1.f, 1.f);
    float4 h = make_float4(0.f, 0.f, 0.f, 0.f);
#pragma unroll 4
    for (int t = 0; t < CHUNK; t++) {
        float4 f = F[base + (size_t)t * (D_ / 4)];
        float4 v = V[base + (size_t)t * (D_ / 4)];
        A.x *= f.x; A.y *= f.y; A.z *= f.z; A.w *= f.w;
        h.x = f.x * h.x + (1.f - f.x) * v.x;
        h.y = f.y * h.y + (1.f - f.y) * v.y;
        h.z = f.z * h.z + (1.f - f.z) * v.z;
        h.w = f.w * h.w + (1.f - f.w) * v.w;
    }
    reinterpret_cast<float4*>(g_cA)[idx] = A;
    reinterpret_cast<float4*>(g_cP)[idx] = h;
}

__global__ void scan_pass2(const float* __restrict__ hidden, float* __restrict__ hT_out)
{
    extern __shared__ float sh[];
    float* sA = sh;
    float* sP = sh + NC * 128;
    const int blk = blockIdx.x;
    const int b   = blk >> 3;
    const int d0  = (blk & 7) * 128;
#pragma unroll 4
    for (int j = 0; j < 64; j++) {
        int i  = threadIdx.x + 256 * j;
        int c  = i >> 7, dd = i & 127;
        size_t g = ((size_t)b * NC + c) * D_ + d0 + dd;
        sA[i] = g_cA[g];
        sP[i] = g_cP[g];
    }
    __syncthreads();
    if (threadIdx.x < 128) {
        const int dd = threadIdx.x;
        float h = hidden[(size_t)b * D_ + d0 + dd];
        for (int c = 0; c < NC; c++) {
            g_cC[((size_t)b * NC + c) * D_ + d0 + dd] = h;
            h = sA[c * 128 + dd] * h + sP[c * 128 + dd];
        }
        hT_out[(size_t)b * D_ + d0 + dd] = h;
    }
}

// emits hs as fp16 (consumed only as GEMM3's A operand)
__global__ void scan_pass3(const float4* __restrict__ V, const float4* __restrict__ F,
                           __half2* __restrict__ HS)
{
    int idx = blockIdx.x * blockDim.x + threadIdx.x;
    int d4 = idx % (D_ / 4);
    int c  = (idx / (D_ / 4)) % NC;
    int b  = idx / ((D_ / 4) * NC);
    size_t base = ((size_t)b * T_ + (size_t)c * CHUNK) * (D_ / 4) + d4;
    float4 h = reinterpret_cast<const float4*>(g_cC)[idx];
#pragma unroll 4
    for (int t = 0; t < CHUNK; t++) {
        float4 f = F[base + (size_t)t * (D_ / 4)];
        float4 v = V[base + (size_t)t * (D_ / 4)];
        h.x = f.x * h.x + (1.f - f.x) * v.x;
        h.y = f.y * h.y + (1.f - f.y) * v.y;
        h.z = f.z * h.z + (1.f - f.z) * v.z;
        h.w = f.w * h.w + (1.f - f.w) * v.w;
        size_t o = (base + (size_t)t * (D_ / 4)) * 2;
        HS[o + 0] = __floats2half2_rn(h.x, h.y);
        HS[o + 1] = __floats2half2_rn(h.z, h.w);
    }
}

// ---------------- LayerNorm ---------------------------------------------------
__global__ __launch_bounds__(256)
void ln_kernel(const float* __restrict__ Z, const float* __restrict__ g,
               const float* __restrict__ b, float* __restrict__ out)
{
    int row = blockIdx.x;
    int t = threadIdx.x;
    float4 x = reinterpret_cast<const float4*>(Z + (size_t)row * D_)[t];
    float s  = x.x + x.y + x.z + x.w;
    float ss = x.x * x.x + x.y * x.y + x.z * x.z + x.w * x.w;
#pragma unroll
    for (int o = 16; o > 0; o >>= 1) {
        s  += __shfl_xor_sync(0xFFFFFFFFu, s, o);
        ss += __shfl_xor_sync(0xFFFFFFFFu, ss, o);
    }
    __shared__ float sh_s[8], sh_ss[8];
    int w = t >> 5, l = t & 31;
    if (l == 0) { sh_s[w] = s; sh_ss[w] = ss; }
    __syncthreads();
    if (w == 0) {
        s  = (l < 8) ? sh_s[l]  : 0.f;
        ss = (l < 8) ? sh_ss[l] : 0.f;
#pragma unroll
        for (int o = 4; o > 0; o >>= 1) {
            s  += __shfl_xor_sync(0xFFFFFFFFu, s, o);
            ss += __shfl_xor_sync(0xFFFFFFFFu, ss, o);
        }
        if (l == 0) { sh_s[0] = s; sh_ss[0] = ss; }
    }
    __syncthreads();
    float mean = sh_s[0] * (1.f / D_);
    float var  = sh_ss[0] * (1.f / D_) - mean * mean;
    float rstd = rsqrtf(var + 1e-5f);
    float4 gg = reinterpret_cast<const float4*>(g)[t];
    float4 bb = reinterpret_cast<const float4*>(b)[t];
    float4 y;
    y.x = (x.x - mean) * rstd * gg.x + bb.x;
    y.y = (x.y - mean) * rstd * gg.y + bb.y;
    y.z = (x.z - mean) * rstd * gg.z + bb.z;
    y.w = (x.w - mean) * rstd * gg.w + bb.w;
    reinterpret_cast<float4*>(out + (size_t)row * D_)[t] = y;
}

// ---------------- launch -------------------------------------------------------
extern "C" void kernel_launch(void* const* d_in, const int* in_sizes, int n_in,
                              void* d_out, int out_size)
{
    const float* x         = (const float*)d_in[0];
    const float* hidden    = (const float*)d_in[1];
    const float* rnn_start = (const float*)d_in[2];
    const float* Win       = (const float*)d_in[3];
    const float* bin_      = (const float*)d_in[4];
    const float* Wout      = (const float*)d_in[5];
    const float* bout      = (const float*)d_in[6];
    const float* W1        = (const float*)d_in[7];
    const float* b1        = (const float*)d_in[8];
    const float* W2        = (const float*)d_in[9];
    const float* b2        = (const float*)d_in[10];
    const float* ln_g      = (const float*)d_in[11];
    const float* ln_b      = (const float*)d_in[12];

    float* out        = (float*)d_out;
    float* hidden_out = out + (size_t)M_ * D_;

    float *buf0, *buf1, *buf2;
    __half* wTh;
    cudaGetSymbolAddress((void**)&buf0, g_buf0);
    cudaGetSymbolAddress((void**)&buf1, g_buf1);
    cudaGetSymbolAddress((void**)&buf2, g_buf2);
    cudaGetSymbolAddress((void**)&wTh,  g_wTh);

    cudaFuncSetAttribute(tgemm_gates,       cudaFuncAttributeMaxDynamicSharedMemorySize, GEMM_SMEM);
    cudaFuncSetAttribute(tgemm<MODE_BIAS>,  cudaFuncAttributeMaxDynamicSharedMemorySize, GEMM_SMEM);
    cudaFuncSetAttribute(tgemm<MODE_GELU>,  cudaFuncAttributeMaxDynamicSharedMemorySize, GEMM_SMEM);
    cudaFuncSetAttribute(tgemm<MODE_RESID>, cudaFuncAttributeMaxDynamicSharedMemorySize, GEMM_SMEM);
    cudaFuncSetAttribute(scan_pass2, cudaFuncAttributeMaxDynamicSharedMemorySize, 2 * NC * 128 * 4);

    __half* xh  = (__half*)buf2;   // fp16 x
    __half* hsh = (__half*)buf2;   // fp16 hs (reuses buf2 after xh dead)
    __half* oh  = (__half*)buf1;   // fp16 out copy (after f dead)
    __half* x_h = (__half*)buf2;   // fp16 gelu output (after hs dead)

    // 0: transpose, 1: cvt_x, 2: aim (no-op), 3: gates GEMM (profiled slot)
    transpose_h<<<dim3(32, 32, 5), dim3(32, 8)>>>(
        Win, Win + (size_t)K_ * D_, Wout, W1, W2, wTh);
    cvt_x_h<<<(M_ * K_) / (256 * 4), 256>>>((const float4*)x, (__half2*)xh);
    aim_kernel<<<1, 32>>>();

    dim3 grid(D_ / BNm, M_ / BMm);        // (8, 128)
    dim3 grid_g(D_ / BNm, M_ / BMm, 2);   // both gates in one launch

    // v -> buf0 ; f -> buf1
    tgemm_gates<<<grid_g, 256, GEMM_SMEM>>>(xh, wTh, bin_, rnn_start, buf0, buf1);

    // chunked scan -> hs (fp16) into buf2, hT -> hidden_out
    scan_pass1<<<(B_ * NC * (D_ / 4)) / 256, 256>>>((const float4*)buf0, (const float4*)buf1);
    scan_pass2<<<32, 256, 2 * NC * 128 * 4>>>(hidden, hidden_out);
    scan_pass3<<<(B_ * NC * (D_ / 4)) / 256, 256>>>((const float4*)buf0, (const float4*)buf1,
                                                    (__half2*)hsh);

    // out = hs@Wout + bout -> buf0 (fp32) + oh (fp16 copy)
    tgemm<MODE_BIAS><<<grid, 256, GEMM_SMEM>>>(hsh, wTh + 2 * (size_t)K_ * D_, bout, nullptr, buf0, oh);
    // x_ = gelu(out@W1 + b1) -> x_h (fp16)
    tgemm<MODE_GELU><<<grid, 256, GEMM_SMEM>>>(oh, wTh + 3 * (size_t)K_ * D_, b1, nullptr, nullptr, x_h);
    // z = x_@W2 + b2 + out -> buf1 (fp32)
    tgemm<MODE_RESID><<<grid, 256, GEMM_SMEM>>>(x_h, wTh + 4 * (size_t)K_ * D_, b2, buf0, buf1, nullptr);
    // out = LN(z)
    ln_kernel<<<M_, 256>>>(buf1, ln_g, ln_b, out);
}

// round 13
// speedup vs baseline: 2.1558x; 1.0260x over previous
#include <cuda_runtime.h>
#include <cuda_fp16.h>
#include <math.h>
#include <stdint.h>

// Problem dims (fixed per setup_inputs)
#define B_   4
#define T_   4096
#define K_   1024          // Din == D == 1024
#define D_   1024
#define M_   (B_*T_)       // 16384

// ---------------- scratch (device globals; no allocations allowed) ---------
__device__ float  g_buf0[(size_t)M_ * D_];   // 64 MB fp32 (reused as half)
__device__ float  g_buf1[(size_t)M_ * D_];   // 64 MB fp32 (reused as half)
__device__ float  g_buf2[(size_t)M_ * D_];   // 64 MB (reused as half)
__device__ __half g_wTh[(size_t)5 * K_ * D_]; // 10 MB transposed fp16 weights

#define CHUNK 32
#define NC    (T_/CHUNK)    // 128
__device__ float g_cA[B_*NC*D_];
__device__ float g_cP[B_*NC*D_];
__device__ float g_cC[B_*NC*D_];

// ---------------- helpers ----------------------------------------------------
__device__ __forceinline__ uint32_t smem_u32(const void* p) {
    uint32_t a;
    asm("{ .reg .u64 t; cvta.to.shared.u64 t, %1; cvt.u32.u64 %0, t; }" : "=r"(a) : "l"(p));
    return a;
}
__device__ __forceinline__ void cp_async16(uint32_t saddr, const void* gptr) {
    asm volatile("cp.async.cg.shared.global [%0], [%1], 16;" :: "r"(saddr), "l"(gptr));
}
#define CP_COMMIT() asm volatile("cp.async.commit_group;" ::: "memory")
#define CP_WAIT1()  asm volatile("cp.async.wait_group 1;"  ::: "memory")
#define CP_WAIT0()  asm volatile("cp.async.wait_group 0;"  ::: "memory")

#define LDSM_X4(r0, r1, r2, r3, addr) \
    asm volatile("ldmatrix.sync.aligned.m8n8.x4.shared.b16 {%0,%1,%2,%3}, [%4];" \
                 : "=r"(r0), "=r"(r1), "=r"(r2), "=r"(r3) : "r"(addr))

__device__ __forceinline__ void mma_f16(float c[4], const uint32_t a[4],
                                        uint32_t b0, uint32_t b1) {
    asm volatile(
        "mma.sync.aligned.m16n8k16.row.col.f32.f16.f16.f32 "
        "{%0,%1,%2,%3}, {%4,%5,%6,%7}, {%8,%9}, {%0,%1,%2,%3};"
        : "+f"(c[0]), "+f"(c[1]), "+f"(c[2]), "+f"(c[3])
        : "r"(a[0]), "r"(a[1]), "r"(a[2]), "r"(a[3]), "r"(b0), "r"(b1));
}

// ---------------- fp16 mma.sync GEMM core (round-12 verified, BK=64) ----------
#define BMm 128
#define BNm 128
#define BKm 64
#define STEPSm (K_/BKm)        // 16
#define STAGE_B 16384          // 128 rows * 128 bytes
#define NSTG 3
#define GEMM_SMEM (2*NSTG*STAGE_B)   // 98304 B

enum { MODE_BIAS = 2, MODE_GELU = 3, MODE_RESID = 4 };

struct Frag { float acc[4][4][4]; };

__device__ __forceinline__ void gemm_mainloop(
    const __half* __restrict__ Ab, const __half* __restrict__ Bb,
    uint32_t sbase, int tid, int lane, int wm, int wn, Frag& fr)
{
    const uint32_t aB = sbase;
    const uint32_t bB = sbase + NSTG * STAGE_B;

    const int r0 = tid >> 3;
    const int g8 = (tid & 7) * 8;
    const uint32_t soff0 = ((uint32_t)r0 << 7)
                         + ((((uint32_t)tid & 7) << 4) ^ (((uint32_t)r0 & 7) << 4));

    const int rr = lane & 7;
    const uint32_t swz   = (uint32_t)rr << 4;
    const uint32_t akoff = (uint32_t)((lane >> 4) & 1) << 4;
    const uint32_t bkoff = (uint32_t)((lane >> 3) & 1) << 4;
    const int a_row8 = (lane >> 3) & 1;
    const int b_n8   = (lane >> 4) & 1;
    uint32_t aoff[4];
#pragma unroll
    for (int mi = 0; mi < 4; mi++)
        aoff[mi] = (uint32_t)(wm * 64 + mi * 16 + a_row8 * 8 + rr) << 7;
    uint32_t boff[2];
#pragma unroll
    for (int j = 0; j < 2; j++)
        boff[j] = (uint32_t)(wn * 32 + j * 16 + b_n8 * 8 + rr) << 7;

#pragma unroll
    for (int mi = 0; mi < 4; mi++)
#pragma unroll
        for (int ni = 0; ni < 4; ni++)
#pragma unroll
            for (int q = 0; q < 4; q++) fr.acc[mi][ni][q] = 0.f;

    uint32_t af[2][4][4];
    uint32_t bq[2][2][4];

#define ISSUE_STAGE(S) do {                                                     \
        const int _k0 = (S) * BKm;                                              \
        const uint32_t _sa = aB + ((S) % NSTG) * STAGE_B + soff0;               \
        const uint32_t _sb = bB + ((S) % NSTG) * STAGE_B + soff0;               \
        _Pragma("unroll")                                                       \
        for (int j = 0; j < 4; j++) {                                           \
            const size_t go = (size_t)(r0 + 32 * j) * K_ + _k0 + g8;            \
            const uint32_t so = (uint32_t)(32 * j) << 7;                        \
            cp_async16(_sa + so, Ab + go);                                      \
            cp_async16(_sb + so, Bb + go);                                      \
        }                                                                       \
    } while (0)

#define LOAD_FRAGS(SLOT, SA, SB, KO) do {                                       \
        const uint32_t _ax = ((KO) + akoff) ^ swz;                              \
        const uint32_t _bx = ((KO) + bkoff) ^ swz;                              \
        _Pragma("unroll")                                                       \
        for (int mi = 0; mi < 4; mi++)                                          \
            LDSM_X4(af[SLOT][mi][0], af[SLOT][mi][1],                           \
                    af[SLOT][mi][2], af[SLOT][mi][3], (SA) + aoff[mi] + _ax);   \
        _Pragma("unroll")                                                       \
        for (int j = 0; j < 2; j++)                                             \
            LDSM_X4(bq[SLOT][j][0], bq[SLOT][j][1],                             \
                    bq[SLOT][j][2], bq[SLOT][j][3], (SB) + boff[j] + _bx);      \
    } while (0)

    ISSUE_STAGE(0); CP_COMMIT();
    ISSUE_STAGE(1); CP_COMMIT();
    CP_WAIT1();
    __syncthreads();

    uint32_t sa = aB, sb = bB;
    LOAD_FRAGS(0, sa, sb, 0u);

    for (int s = 0; s < STEPSm; s++) {
#pragma unroll
        for (int ks = 0; ks < 4; ks++) {
            if (ks < 3) {
                LOAD_FRAGS((ks + 1) & 1, sa, sb, (uint32_t)(ks + 1) * 32);
            } else if (s + 1 < STEPSm) {
                if (s + 2 < STEPSm) { ISSUE_STAGE(s + 2); CP_COMMIT(); CP_WAIT1(); }
                else                { CP_WAIT0(); }
                __syncthreads();
                sa = aB + ((s + 1) % NSTG) * STAGE_B;
                sb = bB + ((s + 1) % NSTG) * STAGE_B;
                LOAD_FRAGS(0, sa, sb, 0u);
            }
            const int p = ks & 1;
#pragma unroll
            for (int mi = 0; mi < 4; mi++)
#pragma unroll
                for (int ni = 0; ni < 4; ni++)
                    mma_f16(fr.acc[mi][ni], af[p][mi],
                            bq[p][ni >> 1][(ni & 1) * 2],
                            bq[p][ni >> 1][(ni & 1) * 2 + 1]);
        }
    }
#undef ISSUE_STAGE
#undef LOAD_FRAGS
}

// ---- chain GEMMs (BIAS / GELU / RESID) --------------------------------------
template <int MODE>
__global__ __launch_bounds__(256, 2)
void tgemm(const __half* __restrict__ A, const __half* __restrict__ Bt,
           const float* __restrict__ bias, const float* __restrict__ extra,
           float* __restrict__ C, __half* __restrict__ Ch)
{
    extern __shared__ float smf[];
    const uint32_t sbase = smem_u32(smf);
    const int tid = threadIdx.x, lane = tid & 31, wid = tid >> 5;
    const int wm = wid >> 2, wn = wid & 3;
    const int bn = blockIdx.x, bm = blockIdx.y;

    Frag fr;
    gemm_mainloop(A + (size_t)bm * BMm * K_, Bt + (size_t)bn * BNm * K_,
                  sbase, tid, lane, wm, wn, fr);

    const int r_base = bm * BMm + wm * 64 + (lane >> 2);
    const int c_base = bn * BNm + wn * 32 + ((lane & 3) << 1);
#pragma unroll
    for (int mi = 0; mi < 4; mi++) {
        const int gr0 = r_base + mi * 16;
        const int gr1 = gr0 + 8;
#pragma unroll
        for (int ni = 0; ni < 4; ni++) {
            const int gc = c_base + ni * 8;
            float b0 = bias[gc], b1 = bias[gc + 1];
            float v0 = fr.acc[mi][ni][0] + b0;
            float v1 = fr.acc[mi][ni][1] + b1;
            float v2 = fr.acc[mi][ni][2] + b0;
            float v3 = fr.acc[mi][ni][3] + b1;
            if (MODE == MODE_GELU) {
                v0 = 0.5f * v0 * (1.f + erff(v0 * 0.70710678118654752f));
                v1 = 0.5f * v1 * (1.f + erff(v1 * 0.70710678118654752f));
                v2 = 0.5f * v2 * (1.f + erff(v2 * 0.70710678118654752f));
                v3 = 0.5f * v3 * (1.f + erff(v3 * 0.70710678118654752f));
                *reinterpret_cast<__half2*>(Ch + (size_t)gr0 * D_ + gc) = __floats2half2_rn(v0, v1);
                *reinterpret_cast<__half2*>(Ch + (size_t)gr1 * D_ + gc) = __floats2half2_rn(v2, v3);
            } else if (MODE == MODE_RESID) {
                const float2 e0 = *reinterpret_cast<const float2*>(extra + (size_t)gr0 * D_ + gc);
                const float2 e1 = *reinterpret_cast<const float2*>(extra + (size_t)gr1 * D_ + gc);
                v0 += e0.x; v1 += e0.y; v2 += e1.x; v3 += e1.y;
                *reinterpret_cast<float2*>(C + (size_t)gr0 * D_ + gc) = make_float2(v0, v1);
                *reinterpret_cast<float2*>(C + (size_t)gr1 * D_ + gc) = make_float2(v2, v3);
            } else {   // MODE_BIAS: fp32 out + fp16 copy
                *reinterpret_cast<float2*>(C + (size_t)gr0 * D_ + gc) = make_float2(v0, v1);
                *reinterpret_cast<float2*>(C + (size_t)gr1 * D_ + gc) = make_float2(v2, v3);
                *reinterpret_cast<__half2*>(Ch + (size_t)gr0 * D_ + gc) = __floats2half2_rn(v0, v1);
                *reinterpret_cast<__half2*>(Ch + (size_t)gr1 * D_ + gc) = __floats2half2_rn(v2, v3);
            }
        }
    }
}

// ---- fused gate GEMMs: outputs stored fp16 (scan consumes) ------------------
__global__ __launch_bounds__(256, 2)
void tgemm_gates(const __half* __restrict__ A, const __half* __restrict__ Wt,
                 const float* __restrict__ bin, const float* __restrict__ rnn_start,
                 __half* __restrict__ Cv, __half* __restrict__ Cf)
{
    extern __shared__ float smf[];
    const uint32_t sbase = smem_u32(smf);
    const int tid = threadIdx.x, lane = tid & 31, wid = tid >> 5;
    const int wm = wid >> 2, wn = wid & 3;
    const int bn = blockIdx.x, bm = blockIdx.y, z = blockIdx.z;

    const __half* Bt  = Wt + (size_t)z * K_ * D_;
    const float* bias = bin + z * D_;

    Frag fr;
    gemm_mainloop(A + (size_t)bm * BMm * K_, Bt + (size_t)bn * BNm * K_,
                  sbase, tid, lane, wm, wn, fr);

    __half* C = z ? Cf : Cv;
    const int r_base = bm * BMm + wm * 64 + (lane >> 2);
    const int c_base = bn * BNm + wn * 32 + ((lane & 3) << 1);
#pragma unroll
    for (int mi = 0; mi < 4; mi++) {
        const int gr0 = r_base + mi * 16;
        const int gr1 = gr0 + 8;
        float rs0 = 0.f, rs1 = 0.f;
        if (z) { rs0 = rnn_start[gr0]; rs1 = rnn_start[gr1]; }
#pragma unroll
        for (int ni = 0; ni < 4; ni++) {
            const int gc = c_base + ni * 8;
            float b0 = bias[gc], b1 = bias[gc + 1];
            float v0 = fr.acc[mi][ni][0] + b0;
            float v1 = fr.acc[mi][ni][1] + b1;
            float v2 = fr.acc[mi][ni][2] + b0;
            float v3 = fr.acc[mi][ni][3] + b1;
            if (z == 0) {
                v0 = tanhf(v0); v1 = tanhf(v1); v2 = tanhf(v2); v3 = tanhf(v3);
            } else {
                v0 = (1.f - rs0) / (1.f + expf(-v0));
                v1 = (1.f - rs0) / (1.f + expf(-v1));
                v2 = (1.f - rs1) / (1.f + expf(-v2));
                v3 = (1.f - rs1) / (1.f + expf(-v3));
            }
            *reinterpret_cast<__half2*>(C + (size_t)gr0 * D_ + gc) = __floats2half2_rn(v0, v1);
            *reinterpret_cast<__half2*>(C + (size_t)gr1 * D_ + gc) = __floats2half2_rn(v2, v3);
        }
    }
}

// ---------------- profiler-aim no-op (keeps gates GEMM at launch index 3) ----
__global__ void aim_kernel() { if (blockIdx.x == 0 && threadIdx.x == 0) g_cA[0] = 0.f; }

// ---------------- x -> fp16 copy ----------------------------------------------
__global__ void cvt_x_h(const float4* __restrict__ x, __half2* __restrict__ xh)
{
    int i = blockIdx.x * blockDim.x + threadIdx.x;
    float4 v = x[i];
    xh[i * 2 + 0] = __floats2half2_rn(v.x, v.y);
    xh[i * 2 + 1] = __floats2half2_rn(v.z, v.w);
}

// ---------------- weight transpose + fp16 -------------------------------------
__global__ void transpose_h(const float* __restrict__ s0, const float* __restrict__ s1,
                            const float* __restrict__ s2, const float* __restrict__ s3,
                            const float* __restrict__ s4, __half* __restrict__ dst)
{
    __shared__ float tile[32][33];
    const int z = blockIdx.z;
    const float* src = (z == 0) ? s0 : (z == 1) ? s1 : (z == 2) ? s2 : (z == 3) ? s3 : s4;
    __half* d = dst + (size_t)z * K_ * D_;
    const int n0 = blockIdx.x * 32, k0 = blockIdx.y * 32;
    const int tx = threadIdx.x, ty = threadIdx.y;
#pragma unroll
    for (int r = 0; r < 32; r += 8)
        tile[ty + r][tx] = src[(size_t)(k0 + ty + r) * D_ + n0 + tx];
    __syncthreads();
#pragma unroll
    for (int r = 0; r < 32; r += 8)
        d[(size_t)(n0 + ty + r) * K_ + k0 + tx] = __float2half_rn(tile[tx][ty + r]);
}

// ---------------- chunked scan: fp16 in, fp32 math ----------------------------
// 8 halves (16B) per thread per timestep; math fp32.
__device__ __forceinline__ void h8_to_f(const uint4 u, float* f) {
    const __half2* p = reinterpret_cast<const __half2*>(&u);
#pragma unroll
    for (int i = 0; i < 4; i++) {
        float2 t = __half22float2(p[i]);
        f[i * 2] = t.x; f[i * 2 + 1] = t.y;
    }
}

__global__ void scan_pass1(const uint4* __restrict__ Vh, const uint4* __restrict__ Fh)
{
    int idx = blockIdx.x * blockDim.x + threadIdx.x;   // over B*NC*(D/8)
    int d8 = idx % (D_ / 8);
    int c  = (idx / (D_ / 8)) % NC;
    int b  = idx / ((D_ / 8) * NC);
    size_t base = ((size_t)b * T_ + (size_t)c * CHUNK) * (D_ / 8) + d8;
    float A[8], h[8];
#pragma unroll
    for (int i = 0; i < 8; i++) { A[i] = 1.f; h[i] = 0.f; }
#pragma unroll 4
    for (int t = 0; t < CHUNK; t++) {
        float f[8], v[8];
        h8_to_f(Fh[base + (size_t)t * (D_ / 8)], f);
        h8_to_f(Vh[base + (size_t)t * (D_ / 8)], v);
#pragma unroll
        for (int i = 0; i < 8; i++) {
            A[i] *= f[i];
            h[i] = f[i] * h[i] + (1.f - f[i]) * v[i];
        }
    }
    float4* pA = reinterpret_cast<float4*>(g_cA) + idx * 2;
    float4* pP = reinterpret_cast<float4*>(g_cP) + idx * 2;
    pA[0] = make_float4(A[0], A[1], A[2], A[3]);
    pA[1] = make_float4(A[4], A[5], A[6], A[7]);
    pP[0] = make_float4(h[0], h[1], h[2], h[3]);
    pP[1] = make_float4(h[4], h[5], h[6], h[7]);
}

__global__ void scan_pass2(const float* __restrict__ hidden, float* __restrict__ hT_out)
{
    extern __shared__ float sh[];
    float* sA = sh;
    float* sP = sh + NC * 128;
    const int blk = blockIdx.x;
    const int b   = blk >> 3;
    const int d0  = (blk & 7) * 128;
#pragma unroll 4
    for (int j = 0; j < 64; j++) {
        int i  = threadIdx.x + 256 * j;
        int c  = i >> 7, dd = i & 127;
        size_t g = ((size_t)b * NC + c) * D_ + d0 + dd;
        sA[i] = g_cA[g];
        sP[i] = g_cP[g];
    }
    __syncthreads();
    if (threadIdx.x < 128) {
        const int dd = threadIdx.x;
        float h = hidden[(size_t)b * D_ + d0 + dd];
        for (int c = 0; c < NC; c++) {
            g_cC[((size_t)b * NC + c) * D_ + d0 + dd] = h;
            h = sA[c * 128 + dd] * h + sP[c * 128 + dd];
        }
        hT_out[(size_t)b * D_ + d0 + dd] = h;
    }
}

// emits hs as fp16 (consumed only as GEMM3's A operand)
__global__ void scan_pass3(const uint4* __restrict__ Vh, const uint4* __restrict__ Fh,
                           uint4* __restrict__ HS)
{
    int idx = blockIdx.x * blockDim.x + threadIdx.x;   // over B*NC*(D/8)
    int d8 = idx % (D_ / 8);
    int c  = (idx / (D_ / 8)) % NC;
    int b  = idx / ((D_ / 8) * NC);
    size_t base = ((size_t)b * T_ + (size_t)c * CHUNK) * (D_ / 8) + d8;
    const float4* pC = reinterpret_cast<const float4*>(g_cC) + idx * 2;
    float4 c0 = pC[0], c1 = pC[1];
    float h[8] = { c0.x, c0.y, c0.z, c0.w, c1.x, c1.y, c1.z, c1.w };
#pragma unroll 4
    for (int t = 0; t < CHUNK; t++) {
        float f[8], v[8];
        h8_to_f(Fh[base + (size_t)t * (D_ / 8)], f);
        h8_to_f(Vh[base + (size_t)t * (D_ / 8)], v);
        uint4 o;
        __half2* po = reinterpret_cast<__half2*>(&o);
#pragma unroll
        for (int i = 0; i < 8; i++)
            h[i] = f[i] * h[i] + (1.f - f[i]) * v[i];
#pragma unroll
        for (int i = 0; i < 4; i++)
            po[i] = __floats2half2_rn(h[i * 2], h[i * 2 + 1]);
        HS[base + (size_t)t * (D_ / 8)] = o;
    }
}

// ---------------- LayerNorm ---------------------------------------------------
__global__ __launch_bounds__(256)
void ln_kernel(const float* __restrict__ Z, const float* __restrict__ g,
               const float* __restrict__ b, float* __restrict__ out)
{
    int row = blockIdx.x;
    int t = threadIdx.x;
    float4 x = reinterpret_cast<const float4*>(Z + (size_t)row * D_)[t];
    float s  = x.x + x.y + x.z + x.w;
    float ss = x.x * x.x + x.y * x.y + x.z * x.z + x.w * x.w;
#pragma unroll
    for (int o = 16; o > 0; o >>= 1) {
        s  += __shfl_xor_sync(0xFFFFFFFFu, s, o);
        ss += __shfl_xor_sync(0xFFFFFFFFu, ss, o);
    }
    __shared__ float sh_s[8], sh_ss[8];
    int w = t >> 5, l = t & 31;
    if (l == 0) { sh_s[w] = s; sh_ss[w] = ss; }
    __syncthreads();
    if (w == 0) {
        s  = (l < 8) ? sh_s[l]  : 0.f;
        ss = (l < 8) ? sh_ss[l] : 0.f;
#pragma unroll
        for (int o = 4; o > 0; o >>= 1) {
            s  += __shfl_xor_sync(0xFFFFFFFFu, s, o);
            ss += __shfl_xor_sync(0xFFFFFFFFu, ss, o);
        }
        if (l == 0) { sh_s[0] = s; sh_ss[0] = ss; }
    }
    __syncthreads();
    float mean = sh_s[0] * (1.f / D_);
    float var  = sh_ss[0] * (1.f / D_) - mean * mean;
    float rstd = rsqrtf(var + 1e-5f);
    float4 gg = reinterpret_cast<const float4*>(g)[t];
    float4 bb = reinterpret_cast<const float4*>(b)[t];
    float4 y;
    y.x = (x.x - mean) * rstd * gg.x + bb.x;
    y.y = (x.y - mean) * rstd * gg.y + bb.y;
    y.z = (x.z - mean) * rstd * gg.z + bb.z;
    y.w = (x.w - mean) * rstd * gg.w + bb.w;
    reinterpret_cast<float4*>(out + (size_t)row * D_)[t] = y;
}

// ---------------- launch -------------------------------------------------------
extern "C" void kernel_launch(void* const* d_in, const int* in_sizes, int n_in,
                              void* d_out, int out_size)
{
    const float* x         = (const float*)d_in[0];
    const float* hidden    = (const float*)d_in[1];
    const float* rnn_start = (const float*)d_in[2];
    const float* Win       = (const float*)d_in[3];
    const float* bin_      = (const float*)d_in[4];
    const float* Wout      = (const float*)d_in[5];
    const float* bout      = (const float*)d_in[6];
    const float* W1        = (const float*)d_in[7];
    const float* b1        = (const float*)d_in[8];
    const float* W2        = (const float*)d_in[9];
    const float* b2        = (const float*)d_in[10];
    const float* ln_g      = (const float*)d_in[11];
    const float* ln_b      = (const float*)d_in[12];

    float* out        = (float*)d_out;
    float* hidden_out = out + (size_t)M_ * D_;

    float *buf0, *buf1, *buf2;
    __half* wTh;
    cudaGetSymbolAddress((void**)&buf0, g_buf0);
    cudaGetSymbolAddress((void**)&buf1, g_buf1);
    cudaGetSymbolAddress((void**)&buf2, g_buf2);
    cudaGetSymbolAddress((void**)&wTh,  g_wTh);

    cudaFuncSetAttribute(tgemm_gates,       cudaFuncAttributeMaxDynamicSharedMemorySize, GEMM_SMEM);
    cudaFuncSetAttribute(tgemm<MODE_BIAS>,  cudaFuncAttributeMaxDynamicSharedMemorySize, GEMM_SMEM);
    cudaFuncSetAttribute(tgemm<MODE_GELU>,  cudaFuncAttributeMaxDynamicSharedMemorySize, GEMM_SMEM);
    cudaFuncSetAttribute(tgemm<MODE_RESID>, cudaFuncAttributeMaxDynamicSharedMemorySize, GEMM_SMEM);
    cudaFuncSetAttribute(scan_pass2, cudaFuncAttributeMaxDynamicSharedMemorySize, 2 * NC * 128 * 4);

    __half* xh  = (__half*)buf2;   // fp16 x
    __half* vh  = (__half*)buf0;   // fp16 v (gate output)
    __half* fh  = (__half*)buf1;   // fp16 f (gate output)
    __half* hsh = (__half*)buf2;   // fp16 hs (reuses buf2 after xh dead)
    __half* oh  = (__half*)buf1;   // fp16 out copy (after f dead)
    __half* x_h = (__half*)buf2;   // fp16 gelu output (after hs dead)

    // 0: transpose, 1: cvt_x, 2: aim (no-op), 3: gates GEMM (profiled slot)
    transpose_h<<<dim3(32, 32, 5), dim3(32, 8)>>>(
        Win, Win + (size_t)K_ * D_, Wout, W1, W2, wTh);
    cvt_x_h<<<(M_ * K_) / (256 * 4), 256>>>((const float4*)x, (__half2*)xh);
    aim_kernel<<<1, 32>>>();

    dim3 grid(D_ / BNm, M_ / BMm);        // (8, 128)
    dim3 grid_g(D_ / BNm, M_ / BMm, 2);   // both gates in one launch

    // v (fp16) -> buf0 ; f (fp16) -> buf1
    tgemm_gates<<<grid_g, 256, GEMM_SMEM>>>(xh, wTh, bin_, rnn_start, vh, fh);

    // chunked scan -> hs (fp16) into buf2, hT -> hidden_out
    scan_pass1<<<(B_ * NC * (D_ / 8)) / 256, 256>>>((const uint4*)vh, (const uint4*)fh);
    scan_pass2<<<32, 256, 2 * NC * 128 * 4>>>(hidden, hidden_out);
    scan_pass3<<<(B_ * NC * (D_ / 8)) / 256, 256>>>((const uint4*)vh, (const uint4*)fh,
                                                    (uint4*)hsh);

    // out = hs@Wout + bout -> buf0 (fp32) + oh (fp16 copy)
    tgemm<MODE_BIAS><<<grid, 256, GEMM_SMEM>>>(hsh, wTh + 2 * (size_t)K_ * D_, bout, nullptr, buf0, oh);
    // x_ = gelu(out@W1 + b1) -> x_h (fp16)
    tgemm<MODE_GELU><<<grid, 256, GEMM_SMEM>>>(oh, wTh + 3 * (size_t)K_ * D_, b1, nullptr, nullptr, x_h);
    // z = x_@W2 + b2 + out -> buf1 (fp32)
    tgemm<MODE_RESID><<<grid, 256, GEMM_SMEM>>>(x_h, wTh + 4 * (size_t)K_ * D_, b2, buf0, buf1, nullptr);
    // out = LN(z)
    ln_kernel<<<M_, 256>>>(buf1, ln_g, ln_b, out);
}

// round 14
// speedup vs baseline: 2.2291x; 1.0340x over previous
#include <cuda_runtime.h>
#include <cuda_fp16.h>
#include <math.h>
#include <stdint.h>

// Problem dims (fixed per setup_inputs)
#define B_   4
#define T_   4096
#define K_   1024          // Din == D == 1024
#define D_   1024
#define M_   (B_*T_)       // 16384

// ---------------- scratch (device globals; no allocations allowed) ---------
__device__ float  g_buf0[(size_t)M_ * D_];   // 64 MB (reused as half)
__device__ float  g_buf1[(size_t)M_ * D_];   // 64 MB (reused as half)
__device__ float  g_buf2[(size_t)M_ * D_];   // 64 MB (reused as half)
__device__ __half g_wTh[(size_t)5 * K_ * D_]; // 10 MB transposed fp16 weights

#define CHUNK 32
#define NC    (T_/CHUNK)    // 128
__device__ float g_cA[B_*NC*D_];
__device__ float g_cP[B_*NC*D_];
__device__ float g_cC[B_*NC*D_];

// ---------------- helpers ----------------------------------------------------
__device__ __forceinline__ uint32_t smem_u32(const void* p) {
    uint32_t a;
    asm("{ .reg .u64 t; cvta.to.shared.u64 t, %1; cvt.u32.u64 %0, t; }" : "=r"(a) : "l"(p));
    return a;
}
__device__ __forceinline__ void cp_async16(uint32_t saddr, const void* gptr) {
    asm volatile("cp.async.cg.shared.global [%0], [%1], 16;" :: "r"(saddr), "l"(gptr));
}
#define CP_COMMIT() asm volatile("cp.async.commit_group;" ::: "memory")
#define CP_WAIT1()  asm volatile("cp.async.wait_group 1;"  ::: "memory")
#define CP_WAIT0()  asm volatile("cp.async.wait_group 0;"  ::: "memory")

#define LDSM_X4(r0, r1, r2, r3, addr) \
    asm volatile("ldmatrix.sync.aligned.m8n8.x4.shared.b16 {%0,%1,%2,%3}, [%4];" \
                 : "=r"(r0), "=r"(r1), "=r"(r2), "=r"(r3) : "r"(addr))

__device__ __forceinline__ void mma_f16(float c[4], const uint32_t a[4],
                                        uint32_t b0, uint32_t b1) {
    asm volatile(
        "mma.sync.aligned.m16n8k16.row.col.f32.f16.f16.f32 "
        "{%0,%1,%2,%3}, {%4,%5,%6,%7}, {%8,%9}, {%0,%1,%2,%3};"
        : "+f"(c[0]), "+f"(c[1]), "+f"(c[2]), "+f"(c[3])
        : "r"(a[0]), "r"(a[1]), "r"(a[2]), "r"(a[3]), "r"(b0), "r"(b1));
}

// ---------------- fp16 mma.sync GEMM core (round-12 verified, BK=64) ----------
#define BMm 128
#define BNm 128
#define BKm 64
#define STEPSm (K_/BKm)        // 16
#define STAGE_B 16384          // 128 rows * 128 bytes
#define NSTG 3
#define GEMM_SMEM (2*NSTG*STAGE_B)   // 98304 B

enum { MODE_BIAS = 2, MODE_GELU = 3, MODE_RESID = 4 };

struct Frag { float acc[4][4][4]; };

__device__ __forceinline__ void gemm_mainloop(
    const __half* __restrict__ Ab, const __half* __restrict__ Bb,
    uint32_t sbase, int tid, int lane, int wm, int wn, Frag& fr)
{
    const uint32_t aB = sbase;
    const uint32_t bB = sbase + NSTG * STAGE_B;

    const int r0 = tid >> 3;
    const int g8 = (tid & 7) * 8;
    const uint32_t soff0 = ((uint32_t)r0 << 7)
                         + ((((uint32_t)tid & 7) << 4) ^ (((uint32_t)r0 & 7) << 4));

    const int rr = lane & 7;
    const uint32_t swz   = (uint32_t)rr << 4;
    const uint32_t akoff = (uint32_t)((lane >> 4) & 1) << 4;
    const uint32_t bkoff = (uint32_t)((lane >> 3) & 1) << 4;
    const int a_row8 = (lane >> 3) & 1;
    const int b_n8   = (lane >> 4) & 1;
    uint32_t aoff[4];
#pragma unroll
    for (int mi = 0; mi < 4; mi++)
        aoff[mi] = (uint32_t)(wm * 64 + mi * 16 + a_row8 * 8 + rr) << 7;
    uint32_t boff[2];
#pragma unroll
    for (int j = 0; j < 2; j++)
        boff[j] = (uint32_t)(wn * 32 + j * 16 + b_n8 * 8 + rr) << 7;

#pragma unroll
    for (int mi = 0; mi < 4; mi++)
#pragma unroll
        for (int ni = 0; ni < 4; ni++)
#pragma unroll
            for (int q = 0; q < 4; q++) fr.acc[mi][ni][q] = 0.f;

    uint32_t af[2][4][4];
    uint32_t bq[2][2][4];

#define ISSUE_STAGE(S) do {                                                     \
        const int _k0 = (S) * BKm;                                              \
        const uint32_t _sa = aB + ((S) % NSTG) * STAGE_B + soff0;               \
        const uint32_t _sb = bB + ((S) % NSTG) * STAGE_B + soff0;               \
        _Pragma("unroll")                                                       \
        for (int j = 0; j < 4; j++) {                                           \
            const size_t go = (size_t)(r0 + 32 * j) * K_ + _k0 + g8;            \
            const uint32_t so = (uint32_t)(32 * j) << 7;                        \
            cp_async16(_sa + so, Ab + go);                                      \
            cp_async16(_sb + so, Bb + go);                                      \
        }                                                                       \
    } while (0)

#define LOAD_FRAGS(SLOT, SA, SB, KO) do {                                       \
        const uint32_t _ax = ((KO) + akoff) ^ swz;                              \
        const uint32_t _bx = ((KO) + bkoff) ^ swz;                              \
        _Pragma("unroll")                                                       \
        for (int mi = 0; mi < 4; mi++)                                          \
            LDSM_X4(af[SLOT][mi][0], af[SLOT][mi][1],                           \
                    af[SLOT][mi][2], af[SLOT][mi][3], (SA) + aoff[mi] + _ax);   \
        _Pragma("unroll")                                                       \
        for (int j = 0; j < 2; j++)                                             \
            LDSM_X4(bq[SLOT][j][0], bq[SLOT][j][1],                             \
                    bq[SLOT][j][2], bq[SLOT][j][3], (SB) + boff[j] + _bx);      \
    } while (0)

    ISSUE_STAGE(0); CP_COMMIT();
    ISSUE_STAGE(1); CP_COMMIT();
    CP_WAIT1();
    __syncthreads();

    uint32_t sa = aB, sb = bB;
    LOAD_FRAGS(0, sa, sb, 0u);

    for (int s = 0; s < STEPSm; s++) {
#pragma unroll
        for (int ks = 0; ks < 4; ks++) {
            if (ks < 3) {
                LOAD_FRAGS((ks + 1) & 1, sa, sb, (uint32_t)(ks + 1) * 32);
            } else if (s + 1 < STEPSm) {
                if (s + 2 < STEPSm) { ISSUE_STAGE(s + 2); CP_COMMIT(); CP_WAIT1(); }
                else                { CP_WAIT0(); }
                __syncthreads();
                sa = aB + ((s + 1) % NSTG) * STAGE_B;
                sb = bB + ((s + 1) % NSTG) * STAGE_B;
                LOAD_FRAGS(0, sa, sb, 0u);
            }
            const int p = ks & 1;
#pragma unroll
            for (int mi = 0; mi < 4; mi++)
#pragma unroll
                for (int ni = 0; ni < 4; ni++)
                    mma_f16(fr.acc[mi][ni], af[p][mi],
                            bq[p][ni >> 1][(ni & 1) * 2],
                            bq[p][ni >> 1][(ni & 1) * 2 + 1]);
        }
    }
#undef ISSUE_STAGE
#undef LOAD_FRAGS
}

// ---- chain GEMMs: all outputs fp16; RESID reads fp16 residual ---------------
template <int MODE>
__global__ __launch_bounds__(256, 2)
void tgemm(const __half* __restrict__ A, const __half* __restrict__ Bt,
           const float* __restrict__ bias, const __half* __restrict__ extra,
           __half* __restrict__ Ch)
{
    extern __shared__ float smf[];
    const uint32_t sbase = smem_u32(smf);
    const int tid = threadIdx.x, lane = tid & 31, wid = tid >> 5;
    const int wm = wid >> 2, wn = wid & 3;
    const int bn = blockIdx.x, bm = blockIdx.y;

    Frag fr;
    gemm_mainloop(A + (size_t)bm * BMm * K_, Bt + (size_t)bn * BNm * K_,
                  sbase, tid, lane, wm, wn, fr);

    const int r_base = bm * BMm + wm * 64 + (lane >> 2);
    const int c_base = bn * BNm + wn * 32 + ((lane & 3) << 1);
#pragma unroll
    for (int mi = 0; mi < 4; mi++) {
        const int gr0 = r_base + mi * 16;
        const int gr1 = gr0 + 8;
#pragma unroll
        for (int ni = 0; ni < 4; ni++) {
            const int gc = c_base + ni * 8;
            float b0 = bias[gc], b1 = bias[gc + 1];
            float v0 = fr.acc[mi][ni][0] + b0;
            float v1 = fr.acc[mi][ni][1] + b1;
            float v2 = fr.acc[mi][ni][2] + b0;
            float v3 = fr.acc[mi][ni][3] + b1;
            if (MODE == MODE_GELU) {
                v0 = 0.5f * v0 * (1.f + erff(v0 * 0.70710678118654752f));
                v1 = 0.5f * v1 * (1.f + erff(v1 * 0.70710678118654752f));
                v2 = 0.5f * v2 * (1.f + erff(v2 * 0.70710678118654752f));
                v3 = 0.5f * v3 * (1.f + erff(v3 * 0.70710678118654752f));
            } else if (MODE == MODE_RESID) {
                float2 e0 = __half22float2(*reinterpret_cast<const __half2*>(extra + (size_t)gr0 * D_ + gc));
                float2 e1 = __half22float2(*reinterpret_cast<const __half2*>(extra + (size_t)gr1 * D_ + gc));
                v0 += e0.x; v1 += e0.y; v2 += e1.x; v3 += e1.y;
            }
            *reinterpret_cast<__half2*>(Ch + (size_t)gr0 * D_ + gc) = __floats2half2_rn(v0, v1);
            *reinterpret_cast<__half2*>(Ch + (size_t)gr1 * D_ + gc) = __floats2half2_rn(v2, v3);
        }
    }
}

// ---- fused gate GEMMs: outputs stored fp16 (scan consumes) ------------------
__global__ __launch_bounds__(256, 2)
void tgemm_gates(const __half* __restrict__ A, const __half* __restrict__ Wt,
                 const float* __restrict__ bin, const float* __restrict__ rnn_start,
                 __half* __restrict__ Cv, __half* __restrict__ Cf)
{
    extern __shared__ float smf[];
    const uint32_t sbase = smem_u32(smf);
    const int tid = threadIdx.x, lane = tid & 31, wid = tid >> 5;
    const int wm = wid >> 2, wn = wid & 3;
    const int bn = blockIdx.x, bm = blockIdx.y, z = blockIdx.z;

    const __half* Bt  = Wt + (size_t)z * K_ * D_;
    const float* bias = bin + z * D_;

    Frag fr;
    gemm_mainloop(A + (size_t)bm * BMm * K_, Bt + (size_t)bn * BNm * K_,
                  sbase, tid, lane, wm, wn, fr);

    __half* C = z ? Cf : Cv;
    const int r_base = bm * BMm + wm * 64 + (lane >> 2);
    const int c_base = bn * BNm + wn * 32 + ((lane & 3) << 1);
#pragma unroll
    for (int mi = 0; mi < 4; mi++) {
        const int gr0 = r_base + mi * 16;
        const int gr1 = gr0 + 8;
        float rs0 = 0.f, rs1 = 0.f;
        if (z) { rs0 = rnn_start[gr0]; rs1 = rnn_start[gr1]; }
#pragma unroll
        for (int ni = 0; ni < 4; ni++) {
            const int gc = c_base + ni * 8;
            float b0 = bias[gc], b1 = bias[gc + 1];
            float v0 = fr.acc[mi][ni][0] + b0;
            float v1 = fr.acc[mi][ni][1] + b1;
            float v2 = fr.acc[mi][ni][2] + b0;
            float v3 = fr.acc[mi][ni][3] + b1;
            if (z == 0) {
                v0 = tanhf(v0); v1 = tanhf(v1); v2 = tanhf(v2); v3 = tanhf(v3);
            } else {
                v0 = (1.f - rs0) / (1.f + expf(-v0));
                v1 = (1.f - rs0) / (1.f + expf(-v1));
                v2 = (1.f - rs1) / (1.f + expf(-v2));
                v3 = (1.f - rs1) / (1.f + expf(-v3));
            }
            *reinterpret_cast<__half2*>(C + (size_t)gr0 * D_ + gc) = __floats2half2_rn(v0, v1);
            *reinterpret_cast<__half2*>(C + (size_t)gr1 * D_ + gc) = __floats2half2_rn(v2, v3);
        }
    }
}

// ---------------- profiler-aim no-op (keeps gates GEMM at launch index 3) ----
__global__ void aim_kernel() { if (blockIdx.x == 0 && threadIdx.x == 0) g_cA[0] = 0.f; }

// ---------------- x -> fp16 copy ----------------------------------------------
__global__ void cvt_x_h(const float4* __restrict__ x, __half2* __restrict__ xh)
{
    int i = blockIdx.x * blockDim.x + threadIdx.x;
    float4 v = x[i];
    xh[i * 2 + 0] = __floats2half2_rn(v.x, v.y);
    xh[i * 2 + 1] = __floats2half2_rn(v.z, v.w);
}

// ---------------- weight transpose + fp16 -------------------------------------
__global__ void transpose_h(const float* __restrict__ s0, const float* __restrict__ s1,
                            const float* __restrict__ s2, const float* __restrict__ s3,
                            const float* __restrict__ s4, __half* __restrict__ dst)
{
    __shared__ float tile[32][33];
    const int z = blockIdx.z;
    const float* src = (z == 0) ? s0 : (z == 1) ? s1 : (z == 2) ? s2 : (z == 3) ? s3 : s4;
    __half* d = dst + (size_t)z * K_ * D_;
    const int n0 = blockIdx.x * 32, k0 = blockIdx.y * 32;
    const int tx = threadIdx.x, ty = threadIdx.y;
#pragma unroll
    for (int r = 0; r < 32; r += 8)
        tile[ty + r][tx] = src[(size_t)(k0 + ty + r) * D_ + n0 + tx];
    __syncthreads();
#pragma unroll
    for (int r = 0; r < 32; r += 8)
        d[(size_t)(n0 + ty + r) * K_ + k0 + tx] = __float2half_rn(tile[tx][ty + r]);
}

// ---------------- chunked scan: fp16 in, fp32 math ----------------------------
__device__ __forceinline__ void h8_to_f(const uint4 u, float* f) {
    const __half2* p = reinterpret_cast<const __half2*>(&u);
#pragma unroll
    for (int i = 0; i < 4; i++) {
        float2 t = __half22float2(p[i]);
        f[i * 2] = t.x; f[i * 2 + 1] = t.y;
    }
}

__global__ void scan_pass1(const uint4* __restrict__ Vh, const uint4* __restrict__ Fh)
{
    int idx = blockIdx.x * blockDim.x + threadIdx.x;
    int d8 = idx % (D_ / 8);
    int c  = (idx / (D_ / 8)) % NC;
    int b  = idx / ((D_ / 8) * NC);
    size_t base = ((size_t)b * T_ + (size_t)c * CHUNK) * (D_ / 8) + d8;
    float A[8], h[8];
#pragma unroll
    for (int i = 0; i < 8; i++) { A[i] = 1.f; h[i] = 0.f; }
#pragma unroll 4
    for (int t = 0; t < CHUNK; t++) {
        float f[8], v[8];
        h8_to_f(Fh[base + (size_t)t * (D_ / 8)], f);
        h8_to_f(Vh[base + (size_t)t * (D_ / 8)], v);
#pragma unroll
        for (int i = 0; i < 8; i++) {
            A[i] *= f[i];
            h[i] = f[i] * h[i] + (1.f - f[i]) * v[i];
        }
    }
    float4* pA = reinterpret_cast<float4*>(g_cA) + idx * 2;
    float4* pP = reinterpret_cast<float4*>(g_cP) + idx * 2;
    pA[0] = make_float4(A[0], A[1], A[2], A[3]);
    pA[1] = make_float4(A[4], A[5], A[6], A[7]);
    pP[0] = make_float4(h[0], h[1], h[2], h[3]);
    pP[1] = make_float4(h[4], h[5], h[6], h[7]);
}

__global__ void scan_pass2(const float* __restrict__ hidden, float* __restrict__ hT_out)
{
    extern __shared__ float sh[];
    float* sA = sh;
    float* sP = sh + NC * 128;
    const int blk = blockIdx.x;
    const int b   = blk >> 3;
    const int d0  = (blk & 7) * 128;
#pragma unroll 4
    for (int j = 0; j < 64; j++) {
        int i  = threadIdx.x + 256 * j;
        int c  = i >> 7, dd = i & 127;
        size_t g = ((size_t)b * NC + c) * D_ + d0 + dd;
        sA[i] = g_cA[g];
        sP[i] = g_cP[g];
    }
    __syncthreads();
    if (threadIdx.x < 128) {
        const int dd = threadIdx.x;
        float h = hidden[(size_t)b * D_ + d0 + dd];
        for (int c = 0; c < NC; c++) {
            g_cC[((size_t)b * NC + c) * D_ + d0 + dd] = h;
            h = sA[c * 128 + dd] * h + sP[c * 128 + dd];
        }
        hT_out[(size_t)b * D_ + d0 + dd] = h;
    }
}

__global__ void scan_pass3(const uint4* __restrict__ Vh, const uint4* __restrict__ Fh,
                           uint4* __restrict__ HS)
{
    int idx = blockIdx.x * blockDim.x + threadIdx.x;
    int d8 = idx % (D_ / 8);
    int c  = (idx / (D_ / 8)) % NC;
    int b  = idx / ((D_ / 8) * NC);
    size_t base = ((size_t)b * T_ + (size_t)c * CHUNK) * (D_ / 8) + d8;
    const float4* pC = reinterpret_cast<const float4*>(g_cC) + idx * 2;
    float4 c0 = pC[0], c1 = pC[1];
    float h[8] = { c0.x, c0.y, c0.z, c0.w, c1.x, c1.y, c1.z, c1.w };
#pragma unroll 4
    for (int t = 0; t < CHUNK; t++) {
        float f[8], v[8];
        h8_to_f(Fh[base + (size_t)t * (D_ / 8)], f);
        h8_to_f(Vh[base + (size_t)t * (D_ / 8)], v);
        uint4 o;
        __half2* po = reinterpret_cast<__half2*>(&o);
#pragma unroll
        for (int i = 0; i < 8; i++)
            h[i] = f[i] * h[i] + (1.f - f[i]) * v[i];
#pragma unroll
        for (int i = 0; i < 4; i++)
            po[i] = __floats2half2_rn(h[i * 2], h[i * 2 + 1]);
        HS[base + (size_t)t * (D_ / 8)] = o;
    }
}

// ---------------- LayerNorm (fp16 input z, fp32 output) ----------------------
__global__ __launch_bounds__(256)
void ln_kernel(const __half* __restrict__ Z, const float* __restrict__ g,
               const float* __restrict__ b, float* __restrict__ out)
{
    int row = blockIdx.x;
    int t = threadIdx.x;   // 256 threads * 4 halves = 1024
    const __half2* zp = reinterpret_cast<const __half2*>(Z + (size_t)row * D_) + t * 2;
    float2 p0 = __half22float2(zp[0]);
    float2 p1 = __half22float2(zp[1]);
    float x0 = p0.x, x1 = p0.y, x2 = p1.x, x3 = p1.y;
    float s  = x0 + x1 + x2 + x3;
    float ss = x0 * x0 + x1 * x1 + x2 * x2 + x3 * x3;
#pragma unroll
    for (int o = 16; o > 0; o >>= 1) {
        s  += __shfl_xor_sync(0xFFFFFFFFu, s, o);
        ss += __shfl_xor_sync(0xFFFFFFFFu, ss, o);
    }
    __shared__ float sh_s[8], sh_ss[8];
    int w = t >> 5, l = t & 31;
    if (l == 0) { sh_s[w] = s; sh_ss[w] = ss; }
    __syncthreads();
    if (w == 0) {
        s  = (l < 8) ? sh_s[l]  : 0.f;
        ss = (l < 8) ? sh_ss[l] : 0.f;
#pragma unroll
        for (int o = 4; o > 0; o >>= 1) {
            s  += __shfl_xor_sync(0xFFFFFFFFu, s, o);
            ss += __shfl_xor_sync(0xFFFFFFFFu, ss, o);
        }
        if (l == 0) { sh_s[0] = s; sh_ss[0] = ss; }
    }
    __syncthreads();
    float mean = sh_s[0] * (1.f / D_);
    float var  = sh_ss[0] * (1.f / D_) - mean * mean;
    float rstd = rsqrtf(var + 1e-5f);
    float4 gg = reinterpret_cast<const float4*>(g)[t];
    float4 bb = reinterpret_cast<const float4*>(b)[t];
    float4 y;
    y.x = (x0 - mean) * rstd * gg.x + bb.x;
    y.y = (x1 - mean) * rstd * gg.y + bb.y;
    y.z = (x2 - mean) * rstd * gg.z + bb.z;
    y.w = (x3 - mean) * rstd * gg.w + bb.w;
    reinterpret_cast<float4*>(out + (size_t)row * D_)[t] = y;
}

// ---------------- launch -------------------------------------------------------
extern "C" void kernel_launch(void* const* d_in, const int* in_sizes, int n_in,
                              void* d_out, int out_size)
{
    const float* x         = (const float*)d_in[0];
    const float* hidden    = (const float*)d_in[1];
    const float* rnn_start = (const float*)d_in[2];
    const float* Win       = (const float*)d_in[3];
    const float* bin_      = (const float*)d_in[4];
    const float* Wout      = (const float*)d_in[5];
    const float* bout      = (const float*)d_in[6];
    const float* W1        = (const float*)d_in[7];
    const float* b1        = (const float*)d_in[8];
    const float* W2        = (const float*)d_in[9];
    const float* b2        = (const float*)d_in[10];
    const float* ln_g      = (const float*)d_in[11];
    const float* ln_b      = (const float*)d_in[12];

    float* out        = (float*)d_out;
    float* hidden_out = out + (size_t)M_ * D_;

    float *buf0, *buf1, *buf2;
    __half* wTh;
    cudaGetSymbolAddress((void**)&buf0, g_buf0);
    cudaGetSymbolAddress((void**)&buf1, g_buf1);
    cudaGetSymbolAddress((void**)&buf2, g_buf2);
    cudaGetSymbolAddress((void**)&wTh,  g_wTh);

    cudaFuncSetAttribute(tgemm_gates,       cudaFuncAttributeMaxDynamicSharedMemorySize, GEMM_SMEM);
    cudaFuncSetAttribute(tgemm<MODE_BIAS>,  cudaFuncAttributeMaxDynamicSharedMemorySize, GEMM_SMEM);
    cudaFuncSetAttribute(tgemm<MODE_GELU>,  cudaFuncAttributeMaxDynamicSharedMemorySize, GEMM_SMEM);
    cudaFuncSetAttribute(tgemm<MODE_RESID>, cudaFuncAttributeMaxDynamicSharedMemorySize, GEMM_SMEM);
    cudaFuncSetAttribute(scan_pass2, cudaFuncAttributeMaxDynamicSharedMemorySize, 2 * NC * 128 * 4);

    __half* xh  = (__half*)buf2;   // fp16 x
    __half* vh  = (__half*)buf0;   // fp16 v (gate output)
    __half* fh  = (__half*)buf1;   // fp16 f (gate output)
    __half* hsh = (__half*)buf2;   // fp16 hs (buf2, after xh dead)
    __half* oh  = (__half*)buf1;   // fp16 out (after f dead)
    __half* x_h = (__half*)buf0;   // fp16 gelu output (after v dead)
    __half* zh  = (__half*)buf2;   // fp16 z (after hs dead)

    // 0: transpose, 1: cvt_x, 2: aim (no-op), 3: gates GEMM (profiled slot)
    transpose_h<<<dim3(32, 32, 5), dim3(32, 8)>>>(
        Win, Win + (size_t)K_ * D_, Wout, W1, W2, wTh);
    cvt_x_h<<<(M_ * K_) / (256 * 4), 256>>>((const float4*)x, (__half2*)xh);
    aim_kernel<<<1, 32>>>();

    dim3 grid(D_ / BNm, M_ / BMm);        // (8, 128)
    dim3 grid_g(D_ / BNm, M_ / BMm, 2);   // both gates in one launch

    // v (fp16) -> buf0 ; f (fp16) -> buf1
    tgemm_gates<<<grid_g, 256, GEMM_SMEM>>>(xh, wTh, bin_, rnn_start, vh, fh);

    // chunked scan -> hs (fp16) into buf2, hT -> hidden_out
    scan_pass1<<<(B_ * NC * (D_ / 8)) / 256, 256>>>((const uint4*)vh, (const uint4*)fh);
    scan_pass2<<<32, 256, 2 * NC * 128 * 4>>>(hidden, hidden_out);
    scan_pass3<<<(B_ * NC * (D_ / 8)) / 256, 256>>>((const uint4*)vh, (const uint4*)fh,
                                                    (uint4*)hsh);

    // out = hs@Wout + bout -> oh (fp16, buf1)
    tgemm<MODE_BIAS><<<grid, 256, GEMM_SMEM>>>(hsh, wTh + 2 * (size_t)K_ * D_, bout, nullptr, oh);
    // x_ = gelu(out@W1 + b1) -> x_h (fp16, buf0)
    tgemm<MODE_GELU><<<grid, 256, GEMM_SMEM>>>(oh, wTh + 3 * (size_t)K_ * D_, b1, nullptr, x_h);
    // z = x_@W2 + b2 + out -> zh (fp16, buf2)
    tgemm<MODE_RESID><<<grid, 256, GEMM_SMEM>>>(x_h, wTh + 4 * (size_t)K_ * D_, b2, oh, zh);
    // out = LN(z)
    ln_kernel<<<M_, 256>>>(zh, ln_g, ln_b, out);
}

// round 16
// speedup vs baseline: 2.2562x; 1.0122x over previous
#include <cuda_runtime.h>
#include <cuda_fp16.h>
#include <math.h>
#include <stdint.h>

// Problem dims (fixed per setup_inputs)
#define B_   4
#define T_   4096
#define K_   1024          // Din == D == 1024
#define D_   1024
#define M_   (B_*T_)       // 16384

// ---------------- scratch (device globals; no allocations allowed) ---------
__device__ float  g_buf0[(size_t)M_ * D_];   // 64 MB (reused as half)
__device__ float  g_buf1[(size_t)M_ * D_];   // 64 MB (reused as half)
__device__ float  g_buf2[(size_t)M_ * D_];   // 64 MB (reused as half)
__device__ __half g_wTh[(size_t)5 * K_ * D_]; // 10 MB transposed fp16 weights
__device__ int    g_cnt[256];                 // [0..127] bias rows, [128..255] gelu rows

#define CHUNK 32
#define NC    (T_/CHUNK)    // 128
__device__ float g_cA[B_*NC*D_];
__device__ float g_cP[B_*NC*D_];
__device__ float g_cC[B_*NC*D_];

// ---------------- helpers ----------------------------------------------------
__device__ __forceinline__ uint32_t smem_u32(const void* p) {
    uint32_t a;
    asm("{ .reg .u64 t; cvta.to.shared.u64 t, %1; cvt.u32.u64 %0, t; }" : "=r"(a) : "l"(p));
    return a;
}
__device__ __forceinline__ void cp_async16(uint32_t saddr, const void* gptr) {
    asm volatile("cp.async.cg.shared.global [%0], [%1], 16;" :: "r"(saddr), "l"(gptr));
}
#define CP_COMMIT() asm volatile("cp.async.commit_group;" ::: "memory")
#define CP_WAIT1()  asm volatile("cp.async.wait_group 1;"  ::: "memory")
#define CP_WAIT0()  asm volatile("cp.async.wait_group 0;"  ::: "memory")

#define LDSM_X4(r0, r1, r2, r3, addr) \
    asm volatile("ldmatrix.sync.aligned.m8n8.x4.shared.b16 {%0,%1,%2,%3}, [%4];" \
                 : "=r"(r0), "=r"(r1), "=r"(r2), "=r"(r3) : "r"(addr))

__device__ __forceinline__ void mma_f16(float c[4], const uint32_t a[4],
                                        uint32_t b0, uint32_t b1) {
    asm volatile(
        "mma.sync.aligned.m16n8k16.row.col.f32.f16.f16.f32 "
        "{%0,%1,%2,%3}, {%4,%5,%6,%7}, {%8,%9}, {%0,%1,%2,%3};"
        : "+f"(c[0]), "+f"(c[1]), "+f"(c[2]), "+f"(c[3])
        : "r"(a[0]), "r"(a[1]), "r"(a[2]), "r"(a[3]), "r"(b0), "r"(b1));
}

__device__ __forceinline__ int ld_acquire(const int* p) {
    int v;
    asm volatile("ld.acquire.gpu.global.s32 %0, [%1];" : "=r"(v) : "l"(p) : "memory");
    return v;
}

// ---------------- fp16 mma.sync GEMM core (round-12 verified, BK=64) ----------
#define BMm 128
#define BNm 128
#define BKm 64
#define STEPSm (K_/BKm)        // 16
#define STAGE_B 16384          // 128 rows * 128 bytes
#define NSTG 3
#define GEMM_SMEM (2*NSTG*STAGE_B)   // 98304 B

struct Frag { float acc[4][4][4]; };

__device__ __forceinline__ void gemm_mainloop(
    const __half* __restrict__ Ab, const __half* __restrict__ Bb,
    uint32_t sbase, int tid, int lane, int wm, int wn, Frag& fr)
{
    const uint32_t aB = sbase;
    const uint32_t bB = sbase + NSTG * STAGE_B;

    const int r0 = tid >> 3;
    const int g8 = (tid & 7) * 8;
    const uint32_t soff0 = ((uint32_t)r0 << 7)
                         + ((((uint32_t)tid & 7) << 4) ^ (((uint32_t)r0 & 7) << 4));

    const int rr = lane & 7;
    const uint32_t swz   = (uint32_t)rr << 4;
    const uint32_t akoff = (uint32_t)((lane >> 4) & 1) << 4;
    const uint32_t bkoff = (uint32_t)((lane >> 3) & 1) << 4;
    const int a_row8 = (lane >> 3) & 1;
    const int b_n8   = (lane >> 4) & 1;
    uint32_t aoff[4];
#pragma unroll
    for (int mi = 0; mi < 4; mi++)
        aoff[mi] = (uint32_t)(wm * 64 + mi * 16 + a_row8 * 8 + rr) << 7;
    uint32_t boff[2];
#pragma unroll
    for (int j = 0; j < 2; j++)
        boff[j] = (uint32_t)(wn * 32 + j * 16 + b_n8 * 8 + rr) << 7;

#pragma unroll
    for (int mi = 0; mi < 4; mi++)
#pragma unroll
        for (int ni = 0; ni < 4; ni++)
#pragma unroll
            for (int q = 0; q < 4; q++) fr.acc[mi][ni][q] = 0.f;

    uint32_t af[2][4][4];
    uint32_t bq[2][2][4];

#define ISSUE_STAGE(S) do {                                                     \
        const int _k0 = (S) * BKm;                                              \
        const uint32_t _sa = aB + ((S) % NSTG) * STAGE_B + soff0;               \
        const uint32_t _sb = bB + ((S) % NSTG) * STAGE_B + soff0;               \
        _Pragma("unroll")                                                       \
        for (int j = 0; j < 4; j++) {                                           \
            const size_t go = (size_t)(r0 + 32 * j) * K_ + _k0 + g8;            \
            const uint32_t so = (uint32_t)(32 * j) << 7;                        \
            cp_async16(_sa + so, Ab + go);                                      \
            cp_async16(_sb + so, Bb + go);                                      \
        }                                                                       \
    } while (0)

#define LOAD_FRAGS(SLOT, SA, SB, KO) do {                                       \
        const uint32_t _ax = ((KO) + akoff) ^ swz;                              \
        const uint32_t _bx = ((KO) + bkoff) ^ swz;                              \
        _Pragma("unroll")                                                       \
        for (int mi = 0; mi < 4; mi++)                                          \
            LDSM_X4(af[SLOT][mi][0], af[SLOT][mi][1],                           \
                    af[SLOT][mi][2], af[SLOT][mi][3], (SA) + aoff[mi] + _ax);   \
        _Pragma("unroll")                                                       \
        for (int j = 0; j < 2; j++)                                             \
            LDSM_X4(bq[SLOT][j][0], bq[SLOT][j][1],                             \
                    bq[SLOT][j][2], bq[SLOT][j][3], (SB) + boff[j] + _bx);      \
    } while (0)

    ISSUE_STAGE(0); CP_COMMIT();
    ISSUE_STAGE(1); CP_COMMIT();
    CP_WAIT1();
    __syncthreads();

    uint32_t sa = aB, sb = bB;
    LOAD_FRAGS(0, sa, sb, 0u);

    for (int s = 0; s < STEPSm; s++) {
#pragma unroll
        for (int ks = 0; ks < 4; ks++) {
            if (ks < 3) {
                LOAD_FRAGS((ks + 1) & 1, sa, sb, (uint32_t)(ks + 1) * 32);
            } else if (s + 1 < STEPSm) {
                if (s + 2 < STEPSm) { ISSUE_STAGE(s + 2); CP_COMMIT(); CP_WAIT1(); }
                else                { CP_WAIT0(); }
                __syncthreads();
                sa = aB + ((s + 1) % NSTG) * STAGE_B;
                sb = bB + ((s + 1) % NSTG) * STAGE_B;
                LOAD_FRAGS(0, sa, sb, 0u);
            }
            const int p = ks & 1;
#pragma unroll
            for (int mi = 0; mi < 4; mi++)
#pragma unroll
                for (int ni = 0; ni < 4; ni++)
                    mma_f16(fr.acc[mi][ni], af[p][mi],
                            bq[p][ni >> 1][(ni & 1) * 2],
                            bq[p][ni >> 1][(ni & 1) * 2 + 1]);
        }
    }
#undef ISSUE_STAGE
#undef LOAD_FRAGS
}

// ---- fused chain: BIAS(stage0) -> GELU(stage1) -> RESID(stage2), one launch --
// Dependencies via per-row-block counters: cnt[bm] (bias done), cnt[128+bm] (gelu done).
__global__ __launch_bounds__(256, 2)
void chain_fused(const __half* __restrict__ hsh,
                 const float* __restrict__ bout, const float* __restrict__ b1,
                 const float* __restrict__ b2,
                 __half* __restrict__ oh, __half* __restrict__ x_h,
                 __half* __restrict__ zh)
{
    extern __shared__ float smf[];
    const uint32_t sbase = smem_u32(smf);
    const int tid = threadIdx.x, lane = tid & 31, wid = tid >> 5;
    const int wm = wid >> 2, wn = wid & 3;

    const int bid   = blockIdx.x;
    const int stage = bid >> 10;          // 0,1,2
    const int t     = bid & 1023;
    const int bm    = t >> 3;             // 0..127 (row-major: row completes fast)
    const int bn    = t & 7;

    const __half* A;
    const __half* Bt;
    const float*  bias;
    if (stage == 0)      { A = hsh; Bt = g_wTh + 2 * (size_t)K_ * D_; bias = bout; }
    else if (stage == 1) { A = oh;  Bt = g_wTh + 3 * (size_t)K_ * D_; bias = b1;   }
    else                 { A = x_h; Bt = g_wTh + 4 * (size_t)K_ * D_; bias = b2;   }

    // consumer wait: producer row-block must be fully written
    if (stage > 0) {
        const int* c = &g_cnt[(stage - 1) * 128 + bm];
        if (tid == 0) {
            while (ld_acquire(c) < 8) __nanosleep(64);
        }
        __syncthreads();
    }

    Frag fr;
    gemm_mainloop(A + (size_t)bm * BMm * K_, Bt + (size_t)bn * BNm * K_,
                  sbase, tid, lane, wm, wn, fr);

    __half* C = (stage == 0) ? oh : (stage == 1) ? x_h : zh;
    const int r_base = bm * BMm + wm * 64 + (lane >> 2);
    const int c_base = bn * BNm + wn * 32 + ((lane & 3) << 1);
#pragma unroll
    for (int mi = 0; mi < 4; mi++) {
        const int gr0 = r_base + mi * 16;
        const int gr1 = gr0 + 8;
#pragma unroll
        for (int ni = 0; ni < 4; ni++) {
            const int gc = c_base + ni * 8;
            float bb0 = bias[gc], bb1 = bias[gc + 1];
            float v0 = fr.acc[mi][ni][0] + bb0;
            float v1 = fr.acc[mi][ni][1] + bb1;
            float v2 = fr.acc[mi][ni][2] + bb0;
            float v3 = fr.acc[mi][ni][3] + bb1;
            if (stage == 1) {
                v0 = 0.5f * v0 * (1.f + erff(v0 * 0.70710678118654752f));
                v1 = 0.5f * v1 * (1.f + erff(v1 * 0.70710678118654752f));
                v2 = 0.5f * v2 * (1.f + erff(v2 * 0.70710678118654752f));
                v3 = 0.5f * v3 * (1.f + erff(v3 * 0.70710678118654752f));
            } else if (stage == 2) {
                float2 e0 = __half22float2(*reinterpret_cast<const __half2*>(oh + (size_t)gr0 * D_ + gc));
                float2 e1 = __half22float2(*reinterpret_cast<const __half2*>(oh + (size_t)gr1 * D_ + gc));
                v0 += e0.x; v1 += e0.y; v2 += e1.x; v3 += e1.y;
            }
            *reinterpret_cast<__half2*>(C + (size_t)gr0 * D_ + gc) = __floats2half2_rn(v0, v1);
            *reinterpret_cast<__half2*>(C + (size_t)gr1 * D_ + gc) = __floats2half2_rn(v2, v3);
        }
    }

    // producer signal (stages 0,1): release stores, then bump row counter
    if (stage < 2) {
        __threadfence();
        __syncthreads();
        if (tid == 0) atomicAdd(&g_cnt[stage * 128 + bm], 1);
    }
}

// ---- fused gate GEMMs: outputs stored fp16 (scan consumes) ------------------
__global__ __launch_bounds__(256, 2)
void tgemm_gates(const __half* __restrict__ A, const __half* __restrict__ Wt,
                 const float* __restrict__ bin, const float* __restrict__ rnn_start,
                 __half* __restrict__ Cv, __half* __restrict__ Cf)
{
    extern __shared__ float smf[];
    const uint32_t sbase = smem_u32(smf);
    const int tid = threadIdx.x, lane = tid & 31, wid = tid >> 5;
    const int wm = wid >> 2, wn = wid & 3;
    const int bn = blockIdx.x, bm = blockIdx.y, z = blockIdx.z;

    const __half* Bt  = Wt + (size_t)z * K_ * D_;
    const float* bias = bin + z * D_;

    Frag fr;
    gemm_mainloop(A + (size_t)bm * BMm * K_, Bt + (size_t)bn * BNm * K_,
                  sbase, tid, lane, wm, wn, fr);

    __half* C = z ? Cf : Cv;
    const int r_base = bm * BMm + wm * 64 + (lane >> 2);
    const int c_base = bn * BNm + wn * 32 + ((lane & 3) << 1);
#pragma unroll
    for (int mi = 0; mi < 4; mi++) {
        const int gr0 = r_base + mi * 16;
        const int gr1 = gr0 + 8;
        float rs0 = 0.f, rs1 = 0.f;
        if (z) { rs0 = rnn_start[gr0]; rs1 = rnn_start[gr1]; }
#pragma unroll
        for (int ni = 0; ni < 4; ni++) {
            const int gc = c_base + ni * 8;
            float b0 = bias[gc], b1 = bias[gc + 1];
            float v0 = fr.acc[mi][ni][0] + b0;
            float v1 = fr.acc[mi][ni][1] + b1;
            float v2 = fr.acc[mi][ni][2] + b0;
            float v3 = fr.acc[mi][ni][3] + b1;
            if (z == 0) {
                v0 = tanhf(v0); v1 = tanhf(v1); v2 = tanhf(v2); v3 = tanhf(v3);
            } else {
                v0 = (1.f - rs0) / (1.f + expf(-v0));
                v1 = (1.f - rs0) / (1.f + expf(-v1));
                v2 = (1.f - rs1) / (1.f + expf(-v2));
                v3 = (1.f - rs1) / (1.f + expf(-v3));
            }
            *reinterpret_cast<__half2*>(C + (size_t)gr0 * D_ + gc) = __floats2half2_rn(v0, v1);
            *reinterpret_cast<__half2*>(C + (size_t)gr1 * D_ + gc) = __floats2half2_rn(v2, v3);
        }
    }
}

// ---------------- x -> fp16 copy ----------------------------------------------
__global__ void cvt_x_h(const float4* __restrict__ x, __half2* __restrict__ xh)
{
    int i = blockIdx.x * blockDim.x + threadIdx.x;
    float4 v = x[i];
    xh[i * 2 + 0] = __floats2half2_rn(v.x, v.y);
    xh[i * 2 + 1] = __floats2half2_rn(v.z, v.w);
}

// ---------------- weight transpose + fp16 -------------------------------------
__global__ void transpose_h(const float* __restrict__ s0, const float* __restrict__ s1,
                            const float* __restrict__ s2, const float* __restrict__ s3,
                            const float* __restrict__ s4, __half* __restrict__ dst)
{
    __shared__ float tile[32][33];
    const int z = blockIdx.z;
    const float* src = (z == 0) ? s0 : (z == 1) ? s1 : (z == 2) ? s2 : (z == 3) ? s3 : s4;
    __half* d = dst + (size_t)z * K_ * D_;
    const int n0 = blockIdx.x * 32, k0 = blockIdx.y * 32;
    const int tx = threadIdx.x, ty = threadIdx.y;
#pragma unroll
    for (int r = 0; r < 32; r += 8)
        tile[ty + r][tx] = src[(size_t)(k0 + ty + r) * D_ + n0 + tx];
    __syncthreads();
#pragma unroll
    for (int r = 0; r < 32; r += 8)
        d[(size_t)(n0 + ty + r) * K_ + k0 + tx] = __float2half_rn(tile[tx][ty + r]);
}

// ---------------- chunked scan: fp16 in, fp32 math ----------------------------
__device__ __forceinline__ void h8_to_f(const uint4 u, float* f) {
    const __half2* p = reinterpret_cast<const __half2*>(&u);
#pragma unroll
    for (int i = 0; i < 4; i++) {
        float2 t = __half22float2(p[i]);
        f[i * 2] = t.x; f[i * 2 + 1] = t.y;
    }
}

__global__ void scan_pass1(const uint4* __restrict__ Vh, const uint4* __restrict__ Fh)
{
    // reset chain counters for this replay (stream-ordered before chain_fused)
    if (blockIdx.x == 0 && threadIdx.x < 256) g_cnt[threadIdx.x] = 0;

    int idx = blockIdx.x * blockDim.x + threadIdx.x;
    int d8 = idx % (D_ / 8);
    int c  = (idx / (D_ / 8)) % NC;
    int b  = idx / ((D_ / 8) * NC);
    size_t base = ((size_t)b * T_ + (size_t)c * CHUNK) * (D_ / 8) + d8;
    float A[8], h[8];
#pragma unroll
    for (int i = 0; i < 8; i++) { A[i] = 1.f; h[i] = 0.f; }
#pragma unroll 4
    for (int t = 0; t < CHUNK; t++) {
        float f[8], v[8];
        h8_to_f(Fh[base + (size_t)t * (D_ / 8)], f);
        h8_to_f(Vh[base + (size_t)t * (D_ / 8)], v);
#pragma unroll
        for (int i = 0; i < 8; i++) {
            A[i] *= f[i];
            h[i] = f[i] * h[i] + (1.f - f[i]) * v[i];
        }
    }
    float4* pA = reinterpret_cast<float4*>(g_cA) + idx * 2;
    float4* pP = reinterpret_cast<float4*>(g_cP) + idx * 2;
    pA[0] = make_float4(A[0], A[1], A[2], A[3]);
    pA[1] = make_float4(A[4], A[5], A[6], A[7]);
    pP[0] = make_float4(h[0], h[1], h[2], h[3]);
    pP[1] = make_float4(h[4], h[5], h[6], h[7]);
}

__global__ void scan_pass2(const float* __restrict__ hidden, float* __restrict__ hT_out)
{
    extern __shared__ float sh[];
    float* sA = sh;
    float* sP = sh + NC * 128;
    const int blk = blockIdx.x;
    const int b   = blk >> 3;
    const int d0  = (blk & 7) * 128;
#pragma unroll 4
    for (int j = 0; j < 64; j++) {
        int i  = threadIdx.x + 256 * j;
        int c  = i >> 7, dd = i & 127;
        size_t g = ((size_t)b * NC + c) * D_ + d0 + dd;
        sA[i] = g_cA[g];
        sP[i] = g_cP[g];
    }
    __syncthreads();
    if (threadIdx.x < 128) {
        const int dd = threadIdx.x;
        float h = hidden[(size_t)b * D_ + d0 + dd];
        for (int c = 0; c < NC; c++) {
            g_cC[((size_t)b * NC + c) * D_ + d0 + dd] = h;
            h = sA[c * 128 + dd] * h + sP[c * 128 + dd];
        }
        hT_out[(size_t)b * D_ + d0 + dd] = h;
    }
}

__global__ void scan_pass3(const uint4* __restrict__ Vh, const uint4* __restrict__ Fh,
                           uint4* __restrict__ HS)
{
    int idx = blockIdx.x * blockDim.x + threadIdx.x;
    int d8 = idx % (D_ / 8);
    int c  = (idx / (D_ / 8)) % NC;
    int b  = idx / ((D_ / 8) * NC);
    size_t base = ((size_t)b * T_ + (size_t)c * CHUNK) * (D_ / 8) + d8;
    const float4* pC = reinterpret_cast<const float4*>(g_cC) + idx * 2;
    float4 c0 = pC[0], c1 = pC[1];
    float h[8] = { c0.x, c0.y, c0.z, c0.w, c1.x, c1.y, c1.z, c1.w };
#pragma unroll 4
    for (int t = 0; t < CHUNK; t++) {
        float f[8], v[8];
        h8_to_f(Fh[base + (size_t)t * (D_ / 8)], f);
        h8_to_f(Vh[base + (size_t)t * (D_ / 8)], v);
        uint4 o;
        __half2* po = reinterpret_cast<__half2*>(&o);
#pragma unroll
        for (int i = 0; i < 8; i++)
            h[i] = f[i] * h[i] + (1.f - f[i]) * v[i];
#pragma unroll
        for (int i = 0; i < 4; i++)
            po[i] = __floats2half2_rn(h[i * 2], h[i * 2 + 1]);
        HS[base + (size_t)t * (D_ / 8)] = o;
    }
}

// ---------------- LayerNorm (fp16 input z, fp32 output) ----------------------
__global__ __launch_bounds__(256)
void ln_kernel(const __half* __restrict__ Z, const float* __restrict__ g,
               const float* __restrict__ b, float* __restrict__ out)
{
    int row = blockIdx.x;
    int t = threadIdx.x;
    const __half2* zp = reinterpret_cast<const __half2*>(Z + (size_t)row * D_) + t * 2;
    float2 p0 = __half22float2(zp[0]);
    float2 p1 = __half22float2(zp[1]);
    float x0 = p0.x, x1 = p0.y, x2 = p1.x, x3 = p1.y;
    float s  = x0 + x1 + x2 + x3;
    float ss = x0 * x0 + x1 * x1 + x2 * x2 + x3 * x3;
#pragma unroll
    for (int o = 16; o > 0; o >>= 1) {
        s  += __shfl_xor_sync(0xFFFFFFFFu, s, o);
        ss += __shfl_xor_sync(0xFFFFFFFFu, ss, o);
    }
    __shared__ float sh_s[8], sh_ss[8];
    int w = t >> 5, l = t & 31;
    if (l == 0) { sh_s[w] = s; sh_ss[w] = ss; }
    __syncthreads();
    if (w == 0) {
        s  = (l < 8) ? sh_s[l]  : 0.f;
        ss = (l < 8) ? sh_ss[l] : 0.f;
#pragma unroll
        for (int o = 4; o > 0; o >>= 1) {
            s  += __shfl_xor_sync(0xFFFFFFFFu, s, o);
            ss += __shfl_xor_sync(0xFFFFFFFFu, ss, o);
        }
        if (l == 0) { sh_s[0] = s; sh_ss[0] = ss; }
    }
    __syncthreads();
    float mean = sh_s[0] * (1.f / D_);
    float var  = sh_ss[0] * (1.f / D_) - mean * mean;
    float rstd = rsqrtf(var + 1e-5f);
    float4 gg = reinterpret_cast<const float4*>(g)[t];
    float4 bb = reinterpret_cast<const float4*>(b)[t];
    float4 y;
    y.x = (x0 - mean) * rstd * gg.x + bb.x;
    y.y = (x1 - mean) * rstd * gg.y + bb.y;
    y.z = (x2 - mean) * rstd * gg.z + bb.z;
    y.w = (x3 - mean) * rstd * gg.w + bb.w;
    reinterpret_cast<float4*>(out + (size_t)row * D_)[t] = y;
}

// ---------------- launch -------------------------------------------------------
extern "C" void kernel_launch(void* const* d_in, const int* in_sizes, int n_in,
                              void* d_out, int out_size)
{
    const float* x         = (const float*)d_in[0];
    const float* hidden    = (const float*)d_in[1];
    const float* rnn_start = (const float*)d_in[2];
    const float* Win       = (const float*)d_in[3];
    const float* bin_      = (const float*)d_in[4];
    const float* Wout      = (const float*)d_in[5];
    const float* bout      = (const float*)d_in[6];
    const float* W1        = (const float*)d_in[7];
    const float* b1        = (const float*)d_in[8];
    const float* W2        = (const float*)d_in[9];
    const float* b2        = (const float*)d_in[10];
    const float* ln_g      = (const float*)d_in[11];
    const float* ln_b      = (const float*)d_in[12];

    float* out        = (float*)d_out;
    float* hidden_out = out + (size_t)M_ * D_;

    float *buf0, *buf1, *buf2;
    __half* wTh;
    cudaGetSymbolAddress((void**)&buf0, g_buf0);
    cudaGetSymbolAddress((void**)&buf1, g_buf1);
    cudaGetSymbolAddress((void**)&buf2, g_buf2);
    cudaGetSymbolAddress((void**)&wTh,  g_wTh);

    cudaFuncSetAttribute(tgemm_gates, cudaFuncAttributeMaxDynamicSharedMemorySize, GEMM_SMEM);
    cudaFuncSetAttribute(chain_fused, cudaFuncAttributeMaxDynamicSharedMemorySize, GEMM_SMEM);
    cudaFuncSetAttribute(scan_pass2,  cudaFuncAttributeMaxDynamicSharedMemorySize, 2 * NC * 128 * 4);

    __half* xh  = (__half*)buf2;   // fp16 x
    __half* vh  = (__half*)buf0;   // fp16 v (gate output)
    __half* fh  = (__half*)buf1;   // fp16 f (gate output)
    __half* hsh = (__half*)buf2;   // fp16 hs (buf2, after xh dead)
    __half* oh  = (__half*)buf1;   // fp16 out (after f dead)
    __half* x_h = (__half*)buf0;   // fp16 gelu output (after v dead)
    __half* zh  = (__half*)((float*)buf2 + (size_t)M_ * D_ / 2);   // fp16 z: 2nd half of buf2
    // NOTE: hsh occupies first 32MB of buf2; zh uses the second 32MB so that
    // chain stage0 (reading hsh) and stage2 (writing zh) never alias.

    // 0: transpose, 1: cvt_x, 2: gates GEMM
    transpose_h<<<dim3(32, 32, 5), dim3(32, 8)>>>(
        Win, Win + (size_t)K_ * D_, Wout, W1, W2, wTh);
    cvt_x_h<<<(M_ * K_) / (256 * 4), 256>>>((const float4*)x, (__half2*)xh);

    dim3 grid_g(8, 128, 2);

    // v (fp16) -> buf0 ; f (fp16) -> buf1
    tgemm_gates<<<grid_g, 256, GEMM_SMEM>>>(xh, wTh, bin_, rnn_start, vh, fh);

    // chunked scan -> hs (fp16) into buf2 (first half), hT -> hidden_out
    scan_pass1<<<(B_ * NC * (D_ / 8)) / 256, 256>>>((const uint4*)vh, (const uint4*)fh);
    scan_pass2<<<32, 256, 2 * NC * 128 * 4>>>(hidden, hidden_out);
    scan_pass3<<<(B_ * NC * (D_ / 8)) / 256, 256>>>((const uint4*)vh, (const uint4*)fh,
                                                    (uint4*)hsh);

    // fused chain: BIAS -> oh(buf1) ; GELU -> x_h(buf0) ; RESID -> zh(buf2 2nd half)
    chain_fused<<<3072, 256, GEMM_SMEM>>>(hsh, bout, b1, b2, oh, x_h, zh);

    // out = LN(z)
    ln_kernel<<<M_, 256>>>(zh, ln_g, ln_b, out);
}